// round 14
// baseline (speedup 1.0000x reference)
#include <cuda_runtime.h>
#include <cuda_bf16.h>
#include <math.h>
#include <stdint.h>

#define DD 8
#define HH 64
#define WW 64
#define LTOK 32768
#define CCH 96
#define CMP 32
#define HID 384
#define HEADS 6
#define HDIM 16
#define NWIN 64
#define NTOK 512

// ---------------- scratch ----------------
__device__ __nv_bfloat16 g_xn  [LTOK * CCH];
__device__ __nv_bfloat16 g_y1  [LTOK * CMP];
__device__ __nv_bfloat16 g_y2  [LTOK * CCH];
__device__ float         g_part[512 * CCH];
__device__ float         g_att [CCH];
__device__ __nv_bfloat16 g_qkv [LTOK * 3 * CCH];   // [type][win][head][512][16]
__device__ __nv_bfloat16 g_bias[HEADS * NTOK * NTOK];
__device__ __nv_bfloat16 g_o   [LTOK * CCH];
__device__ float         g_x1  [LTOK * CCH];
__device__ __nv_bfloat16 g_xn2 [LTOK * CCH];
__device__ __nv_bfloat16 g_w1r [27 * CMP * CCH];
__device__ __nv_bfloat16 g_w2r [27 * CCH * CMP];
__device__ __nv_bfloat16 g_qw  [288 * 96];
__device__ __nv_bfloat16 g_pw  [96 * 96];
__device__ __nv_bfloat16 g_f1w [384 * 96];
__device__ __nv_bfloat16 g_f2w [96 * 384];

__device__ __forceinline__ float gelu_exact(float v) {
    return 0.5f * v * (1.0f + erff(v * 0.70710678118654752f));
}
__device__ __forceinline__ unsigned pack2(float a, float b) {
    __nv_bfloat162 t = __floats2bfloat162_rn(a, b);
    return *reinterpret_cast<unsigned*>(&t);
}
__device__ __forceinline__ void ldsm4(unsigned* r, unsigned addr) {
    asm volatile("ldmatrix.sync.aligned.m8n8.x4.shared.b16 {%0,%1,%2,%3},[%4];"
                 : "=r"(r[0]), "=r"(r[1]), "=r"(r[2]), "=r"(r[3]) : "r"(addr));
}
__device__ __forceinline__ void ldsmB(unsigned* r, const __nv_bfloat16* base, int S, int lane) {
    int tq = lane & 7, sel = lane >> 3;
    const __nv_bfloat16* p = base + ((sel & 2) * 4 + tq) * S + (sel & 1) * 8;
    ldsm4(r, (unsigned)__cvta_generic_to_shared(p));
}
__device__ __forceinline__ void mma16(float* d, const unsigned* a, const unsigned* b) {
    asm volatile(
        "mma.sync.aligned.m16n8k16.row.col.f32.bf16.bf16.f32 "
        "{%0,%1,%2,%3},{%4,%5,%6,%7},{%8,%9},{%0,%1,%2,%3};"
        : "+f"(d[0]), "+f"(d[1]), "+f"(d[2]), "+f"(d[3])
        : "r"(a[0]), "r"(a[1]), "r"(a[2]), "r"(a[3]), "r"(b[0]), "r"(b[1]));
}
__device__ __forceinline__ void cpa16(__nv_bfloat16* s, const void* g, bool v) {
    unsigned sa = (unsigned)__cvta_generic_to_shared(s);
    int sz = v ? 16 : 0;
    asm volatile("cp.async.cg.shared.global [%0], [%1], 16, %2;" :: "r"(sa), "l"(g), "r"(sz));
}
__device__ __forceinline__ void cpa_commit() { asm volatile("cp.async.commit_group;"); }
template <int N> __device__ __forceinline__ void cpa_wait() {
    asm volatile("cp.async.wait_group %0;" :: "n"(N));
}

// ---------------- LayerNorm (feeds conv branch only) ----------------
__global__ void ln_kernel(const float* __restrict__ x, const float* __restrict__ g,
                          const float* __restrict__ b, __nv_bfloat16* __restrict__ out)
{
    int row  = blockIdx.x * 8 + (threadIdx.x >> 5);
    int lane = threadIdx.x & 31;
    const float* xr = x + (size_t)row * CCH;
    float v0 = xr[lane], v1 = xr[lane + 32], v2 = xr[lane + 64];
    float s = v0 + v1 + v2;
    #pragma unroll
    for (int o = 16; o; o >>= 1) s += __shfl_xor_sync(0xffffffffu, s, o);
    float mu = s * (1.0f / 96.0f);
    float d0 = v0 - mu, d1 = v1 - mu, d2 = v2 - mu;
    float q = d0 * d0 + d1 * d1 + d2 * d2;
    #pragma unroll
    for (int o = 16; o; o >>= 1) q += __shfl_xor_sync(0xffffffffu, q, o);
    float inv = rsqrtf(q * (1.0f / 96.0f) + 1e-5f);
    __nv_bfloat16* orow = out + (size_t)row * CCH;
    orow[lane]      = __float2bfloat16(d0 * inv * g[lane]      + b[lane]);
    orow[lane + 32] = __float2bfloat16(d1 * inv * g[lane + 32] + b[lane + 32]);
    orow[lane + 64] = __float2bfloat16(d2 * inv * g[lane + 64] + b[lane + 64]);
}

// ---------------- setup: weights only (1080 blocks) ----------------
__global__ void setup_w_kernel(
    const float* __restrict__ qkv_w, const float* __restrict__ proj_w,
    const float* __restrict__ fc1_w, const float* __restrict__ fc2_w,
    const float* __restrict__ conv1_w, const float* __restrict__ conv2_w,
    __nv_bfloat16* __restrict__ qw, __nv_bfloat16* __restrict__ pw,
    __nv_bfloat16* __restrict__ f1w, __nv_bfloat16* __restrict__ f2w,
    __nv_bfloat16* __restrict__ w1r, __nv_bfloat16* __restrict__ w2r)
{
    int b = blockIdx.x, tx = threadIdx.x;
    if (b < 108) {
        int i = b * 256 + tx;
        if (i < 288 * 96) qw[i] = __float2bfloat16(qkv_w[i]);
    } else if (b < 144) {
        int i = (b - 108) * 256 + tx;
        if (i < 96 * 96) pw[i] = __float2bfloat16(proj_w[i]);
    } else if (b < 288) {
        int i = (b - 144) * 256 + tx;
        if (i < 384 * 96) f1w[i] = __float2bfloat16(fc1_w[i]);
    } else if (b < 432) {
        int i = (b - 288) * 256 + tx;
        if (i < 96 * 384) f2w[i] = __float2bfloat16(fc2_w[i]);
    } else if (b < 756) {
        int tid = (b - 432) * 256 + tx;
        if (tid < CMP * CCH * 27) {
            int o = tid / (CCH * 27);
            int rem = tid - o * (CCH * 27);
            int c = rem / 27;
            int tap = rem - c * 27;
            w1r[(tap * CMP + o) * CCH + c] = __float2bfloat16(conv1_w[tid]);
        }
    } else {
        int tid = (b - 756) * 256 + tx;
        if (tid < CCH * CMP * 27) {
            int o = tid / (CMP * 27);
            int rem = tid - o * (CMP * 27);
            int i = rem / 27;
            int tap = rem - i * 27;
            w2r[(tap * CCH + o) * CMP + i] = __float2bfloat16(conv2_w[tid]);
        }
    }
}

// ---------------- setup: bias expansion ----------------
__global__ void setup_bias_kernel(const int* __restrict__ rpi, const float* __restrict__ rpbt,
                                  __nv_bfloat16* __restrict__ biasb)
{
    int tid = blockIdx.x * 256 + threadIdx.x;
    int e = tid * 2;
    int h = e >> 18;
    int r = e & 262143;
    int2 ri = *(const int2*)(rpi + r);
    *(unsigned*)(biasb + e) = pack2(rpbt[ri.x * HEADS + h], rpbt[ri.y * HEADS + h]);
}

// ---------------- conv1: 96->32 + GELU, 2-stage cp.async ----------------
#define C1_SE (162 * 104)
__global__ __launch_bounds__(256) void conv1_kernel(
    const __nv_bfloat16* __restrict__ xn, const __nv_bfloat16* __restrict__ w1r,
    const float* __restrict__ b1, __nv_bfloat16* __restrict__ y1)
{
    extern __shared__ __nv_bfloat16 smb[];
    int d = blockIdx.x >> 6, h = blockIdx.x & 63;
    int tx = threadIdx.x;
    int warp = tx >> 5, lane = tx & 31;
    int gid = lane >> 2, tig = lane & 3;
    int wm = warp >> 1, wn = warp & 1;
    float acc[2][4] = {};

    auto load_phase = [&](int p, int buf) {
        int kd = p / 3, kh = p - kd * 3;
        int dd = d + kd - 1, hh = h + kh - 1;
        bool rowv = ((unsigned)dd < 8u) && ((unsigned)hh < 64u);
        __nv_bfloat16* in_s = smb + buf * C1_SE;
        __nv_bfloat16* w_s  = in_s + 66 * 104;
        const __nv_bfloat16* src_row = xn + ((size_t)(dd * HH + hh) * WW) * CCH;
        for (int idx = tx; idx < 792; idx += 256) {
            int r = idx / 12, c = idx - r * 12;
            int wv = r - 1;
            bool v = rowv && (unsigned)wv < 64u;
            const void* g = v ? (const void*)(src_row + wv * CCH + c * 8) : (const void*)xn;
            cpa16(in_s + r * 104 + c * 8, g, v);
        }
        const __nv_bfloat16* wsrc = w1r + (size_t)p * 3 * (CMP * CCH);
        for (int idx = tx; idx < 1152; idx += 256) {
            int r = idx / 12, c = idx - r * 12;
            cpa16(w_s + r * 104 + c * 8, wsrc + idx * 8, true);
        }
        cpa_commit();
    };

    load_phase(0, 0);
    for (int p = 0; p < 9; p++) {
        cpa_wait<0>();
        __syncthreads();
        if (p < 8) load_phase(p + 1, (p + 1) & 1);
        __nv_bfloat16* in_s = smb + (p & 1) * C1_SE;
        __nv_bfloat16* w_s  = in_s + 66 * 104;
        unsigned in_u = (unsigned)__cvta_generic_to_shared(in_s);
        #pragma unroll
        for (int kw = 0; kw < 3; kw++) {
            #pragma unroll
            for (int ks = 0; ks < 6; ks++) {
                unsigned af[4];
                ldsm4(af, in_u + 2u * ((wm * 16 + kw + (lane & 15)) * 104
                                       + ks * 16 + ((lane >> 4) << 3)));
                unsigned bf[4];
                ldsmB(bf, w_s + (kw * 32 + wn * 16) * 104 + ks * 16, 104, lane);
                mma16(acc[0], af, bf);
                mma16(acc[1], af, bf + 2);
            }
        }
    }
    __nv_bfloat16* orow = y1 + (size_t)(d * HH + h) * WW * CMP;
    #pragma unroll
    for (int nt = 0; nt < 2; nt++) {
        int oc = wn * 16 + nt * 8 + tig * 2;
        float bb0 = b1[oc], bb1 = b1[oc + 1];
        #pragma unroll
        for (int half = 0; half < 2; half++) {
            int v = wm * 16 + gid + half * 8;
            *(unsigned*)(orow + v * CMP + oc) =
                pack2(gelu_exact(acc[nt][half * 2 + 0] + bb0),
                      gelu_exact(acc[nt][half * 2 + 1] + bb1));
        }
    }
}

// ---------------- conv2: 32->96, 2-stage cp.async + fused pool partials ----------------
#define C2_SE (354 * 40)
__global__ __launch_bounds__(256) void conv2_kernel(
    const __nv_bfloat16* __restrict__ y1, const __nv_bfloat16* __restrict__ w2r,
    const float* __restrict__ b2, __nv_bfloat16* __restrict__ y2, float* __restrict__ part)
{
    extern __shared__ __nv_bfloat16 smb[];
    int d = blockIdx.x >> 6, h = blockIdx.x & 63;
    int tx = threadIdx.x;
    int warp = tx >> 5, lane = tx & 31;
    int gid = lane >> 2, tig = lane & 3;
    int wm = warp >> 1, wn = warp & 1;
    float acc[6][4] = {};

    auto load_phase = [&](int p, int buf) {
        int kd = p / 3, kh = p - kd * 3;
        int dd = d + kd - 1, hh = h + kh - 1;
        bool rowv = ((unsigned)dd < 8u) && ((unsigned)hh < 64u);
        __nv_bfloat16* in_s = smb + buf * C2_SE;
        __nv_bfloat16* w_s  = in_s + 66 * 40;
        const __nv_bfloat16* src_row = y1 + ((size_t)(dd * HH + hh) * WW) * CMP;
        for (int idx = tx; idx < 264; idx += 256) {
            int r = idx >> 2, c = idx & 3;
            int wv = r - 1;
            bool v = rowv && (unsigned)wv < 64u;
            const void* g = v ? (const void*)(src_row + wv * CMP + c * 8) : (const void*)y1;
            cpa16(in_s + r * 40 + c * 8, g, v);
        }
        const __nv_bfloat16* wsrc = w2r + (size_t)p * 3 * (CCH * CMP);
        for (int idx = tx; idx < 1152; idx += 256) {
            int r = idx >> 2, c = idx & 3;
            cpa16(w_s + r * 40 + c * 8, wsrc + idx * 8, true);
        }
        cpa_commit();
    };

    load_phase(0, 0);
    for (int p = 0; p < 9; p++) {
        cpa_wait<0>();
        __syncthreads();
        if (p < 8) load_phase(p + 1, (p + 1) & 1);
        __nv_bfloat16* in_s = smb + (p & 1) * C2_SE;
        __nv_bfloat16* w_s  = in_s + 66 * 40;
        unsigned in_u = (unsigned)__cvta_generic_to_shared(in_s);
        #pragma unroll
        for (int kw = 0; kw < 3; kw++) {
            #pragma unroll
            for (int ks = 0; ks < 2; ks++) {
                unsigned af[4];
                ldsm4(af, in_u + 2u * ((wm * 16 + kw + (lane & 15)) * 40
                                       + ks * 16 + ((lane >> 4) << 3)));
                #pragma unroll
                for (int np = 0; np < 3; np++) {
                    unsigned bf[4];
                    ldsmB(bf, w_s + (kw * 96 + wn * 48 + np * 16) * 40 + ks * 16, 40, lane);
                    mma16(acc[np * 2], af, bf);
                    mma16(acc[np * 2 + 1], af, bf + 2);
                }
            }
        }
    }
    __nv_bfloat16* orow = y2 + (size_t)(d * HH + h) * WW * CCH;
    float ch0[6], ch1[6];
    #pragma unroll
    for (int nt = 0; nt < 6; nt++) {
        int oc = wn * 48 + nt * 8 + tig * 2;
        float bb0 = b2[oc], bb1 = b2[oc + 1];
        #pragma unroll
        for (int half = 0; half < 2; half++) {
            int v = wm * 16 + gid + half * 8;
            *(unsigned*)(orow + v * CCH + oc) =
                pack2(acc[nt][half * 2 + 0] + bb0, acc[nt][half * 2 + 1] + bb1);
        }
        ch0[nt] = acc[nt][0] + acc[nt][2] + 2.0f * bb0;
        ch1[nt] = acc[nt][1] + acc[nt][3] + 2.0f * bb1;
    }
    #pragma unroll
    for (int nt = 0; nt < 6; nt++) {
        #pragma unroll
        for (int m = 4; m < 32; m <<= 1) {
            ch0[nt] += __shfl_xor_sync(0xffffffffu, ch0[nt], m);
            ch1[nt] += __shfl_xor_sync(0xffffffffu, ch1[nt], m);
        }
    }
    __syncthreads();
    float* ws = (float*)smb;
    if (gid == 0) {
        #pragma unroll
        for (int nt = 0; nt < 6; nt++) {
            int oc = wn * 48 + nt * 8 + tig * 2;
            ws[warp * 96 + oc] = ch0[nt];
            ws[warp * 96 + oc + 1] = ch1[nt];
        }
    }
    __syncthreads();
    if (tx < 96) {
        int wn2 = tx / 48;
        float s = ws[wn2 * 96 + tx] + ws[(wn2 + 2) * 96 + tx]
                + ws[(wn2 + 4) * 96 + tx] + ws[(wn2 + 6) * 96 + tx];
        part[blockIdx.x * 96 + tx] = s;
    }
}

// ---------------- channel attention ----------------
__global__ void ca_kernel(const float* __restrict__ part,
                          const float* __restrict__ ca1w, const float* __restrict__ ca1b,
                          const float* __restrict__ ca2w, const float* __restrict__ ca2b,
                          float* __restrict__ att)
{
    __shared__ float p[CCH], hs[3];
    int tx = threadIdx.x;
    float s = 0.f;
    for (int b = 0; b < 512; b++) s += part[b * CCH + tx];
    p[tx] = s * (1.0f / (float)LTOK);
    __syncthreads();
    if (tx < 3) {
        float a = ca1b[tx];
        for (int c = 0; c < CCH; c++) a += ca1w[tx * CCH + c] * p[c];
        hs[tx] = fmaxf(a, 0.f);
    }
    __syncthreads();
    float a = ca2b[tx];
    #pragma unroll
    for (int k = 0; k < 3; k++) a += ca2w[tx * 3 + k] * hs[k];
    att[tx] = 1.0f / (1.0f + expf(-a));
}

// ---------------- fused LN1 + qkv GEMM, window-ordered output ----------------
// out layout: [type(=blockIdx.y)][win][head][j:512][hd:16]
#define QKV_XS (224 * 104)      // fp32 x tile after a_s + w_s (in bf16-elem units)
__global__ __launch_bounds__(256) void gemm_qkv_ln(
    const float* __restrict__ x, const float* __restrict__ n1g, const float* __restrict__ n1b,
    const __nv_bfloat16* __restrict__ Wt, const float* __restrict__ bias,
    __nv_bfloat16* __restrict__ Cout)
{
    extern __shared__ __nv_bfloat16 smb[];
    __nv_bfloat16* a_s = smb;
    __nv_bfloat16* w_s = smb + 128 * 104;
    float* xs = (float*)(smb + QKV_XS);
    int m0 = blockIdx.x * 128, n0 = blockIdx.y * 96;
    int tx = threadIdx.x;
    int warp = tx >> 5, lane = tx & 31;
    int wm = warp >> 1, wn = warp & 1;
    int gid = lane >> 2, tig = lane & 3;

    // weights via cp.async (overlap with LN)
    for (int idx = tx; idx < 1152; idx += 256) {
        int r = idx / 12, c = idx - r * 12;
        cpa16(w_s + r * 104 + c * 8, Wt + (size_t)(n0 + r) * 96 + c * 8, true);
    }
    cpa_commit();
    // x tile fp32
    for (int idx = tx; idx < 3072; idx += 256) {
        int r = idx / 24, c = idx - r * 24;
        *(float4*)(xs + r * 96 + c * 4) = *(const float4*)(x + (size_t)(m0 + r) * 96 + c * 4);
    }
    __syncthreads();
    // LN: 2 threads per row
    {
        int row = tx >> 1, half = tx & 1;
        const float* xr = xs + row * 96 + half * 48;
        float s = 0.f, q = 0.f;
        #pragma unroll
        for (int i = 0; i < 48; i++) { float v = xr[i]; s += v; q += v * v; }
        s += __shfl_xor_sync(0xffffffffu, s, 1);
        q += __shfl_xor_sync(0xffffffffu, q, 1);
        float mu = s * (1.0f / 96.0f);
        float inv = rsqrtf(q * (1.0f / 96.0f) - mu * mu + 1e-5f);
        __nv_bfloat16* ar = a_s + row * 104 + half * 48;
        const float* gg = n1g + half * 48;
        const float* bb = n1b + half * 48;
        #pragma unroll
        for (int i = 0; i < 24; i++) {
            float v0 = (xr[2 * i]     - mu) * inv * gg[2 * i]     + bb[2 * i];
            float v1 = (xr[2 * i + 1] - mu) * inv * gg[2 * i + 1] + bb[2 * i + 1];
            *(unsigned*)(ar + 2 * i) = pack2(v0, v1);
        }
    }
    cpa_wait<0>();
    __syncthreads();

    float acc[2][6][4] = {};
    unsigned a_u = (unsigned)__cvta_generic_to_shared(a_s);
    #pragma unroll
    for (int ks = 0; ks < 6; ks++) {
        unsigned af[2][4];
        #pragma unroll
        for (int mt = 0; mt < 2; mt++)
            ldsm4(af[mt], a_u + 2u * ((wm * 32 + mt * 16 + (lane & 15)) * 104
                                      + ks * 16 + ((lane >> 4) << 3)));
        #pragma unroll
        for (int np = 0; np < 3; np++) {
            unsigned bf[4];
            ldsmB(bf, w_s + (wn * 48 + np * 16) * 104 + ks * 16, 104, lane);
            #pragma unroll
            for (int mt = 0; mt < 2; mt++) {
                mma16(acc[mt][np * 2], af[mt], bf);
                mma16(acc[mt][np * 2 + 1], af[mt], bf + 2);
            }
        }
    }
    // epilogue: window-ordered store
    int type = blockIdx.y;
    #pragma unroll
    for (int mt = 0; mt < 2; mt++) {
        #pragma unroll
        for (int half = 0; half < 2; half++) {
            int r = m0 + wm * 32 + mt * 16 + gid + half * 8;
            int d = r >> 12, rem = r & 4095;
            int hh = rem >> 6, ww = rem & 63;
            int win = ((hh >> 3) << 3) + (ww >> 3);
            int j = (d << 6) + ((hh & 7) << 3) + (ww & 7);
            #pragma unroll
            for (int nt = 0; nt < 6; nt++) {
                int ch = wn * 48 + nt * 8 + tig * 2;
                int cc = n0 + ch;
                int head = ch >> 4, hd = ch & 15;
                float bb0 = bias[cc], bb1 = bias[cc + 1];
                size_t addr = ((size_t)((type * 64 + win) * 6 + head) << 13) + (j << 4) + hd;
                *(unsigned*)(Cout + addr) = pack2(acc[mt][nt][half * 2 + 0] + bb0,
                                                  acc[mt][nt][half * 2 + 1] + bb1);
            }
        }
    }
}

// ---------------- fused MLP ----------------
#define MLP_A  0
#define MLP_W  (64 * 104)
#define MLP_H  (MLP_W + 2 * 96 * 104)
#define MLP_SE (MLP_H + 4 * 64 * 104)
__global__ __launch_bounds__(256) void mlp_kernel(
    const __nv_bfloat16* __restrict__ xn2, const __nv_bfloat16* __restrict__ f1w,
    const float* __restrict__ fb1, const __nv_bfloat16* __restrict__ f2w,
    const float* __restrict__ fb2, const float* __restrict__ x1,
    float* __restrict__ out)
{
    extern __shared__ __nv_bfloat16 smb[];
    __nv_bfloat16* a_s = smb + MLP_A;
    __nv_bfloat16* h_s = smb + MLP_H;
    int m0 = blockIdx.x * 64;
    int tx = threadIdx.x;
    int warp = tx >> 5, lane = tx & 31;
    int wm = warp >> 1, wn = warp & 1;
    int gid = lane >> 2, tig = lane & 3;

    for (int idx = tx; idx < 768; idx += 256) {
        int r = idx / 12, c = idx - r * 12;
        *(uint4*)(a_s + r * 104 + c * 8) = *(const uint4*)(xn2 + (size_t)(m0 + r) * 96 + c * 8);
    }
    auto load_w = [&](int ph, int buf) {
        __nv_bfloat16* w_s = smb + MLP_W + buf * (96 * 104);
        const __nv_bfloat16* src = (ph < 4)
            ? f1w + (size_t)(ph * 96) * 96
            : f2w + (size_t)(ph - 4) * 96;
        size_t rstride = (ph < 4) ? 96 : 384;
        for (int idx = tx; idx < 1152; idx += 256) {
            int r = idx / 12, c = idx - r * 12;
            cpa16(w_s + r * 104 + c * 8, src + (size_t)r * rstride + c * 8, true);
        }
        cpa_commit();
    };
    load_w(0, 0);

    float acc[6][4] = {};
    unsigned a_u = (unsigned)__cvta_generic_to_shared(a_s);
    unsigned h_u = (unsigned)__cvta_generic_to_shared(h_s);

    for (int ph = 0; ph < 8; ph++) {
        cpa_wait<0>();
        __syncthreads();
        if (ph < 7) load_w(ph + 1, (ph + 1) & 1);
        __nv_bfloat16* w_s = smb + MLP_W + (ph & 1) * (96 * 104);
        if (ph < 4) {
            #pragma unroll
            for (int nt = 0; nt < 6; nt++)
                #pragma unroll
                for (int e = 0; e < 4; e++) acc[nt][e] = 0.f;
            #pragma unroll
            for (int ks = 0; ks < 6; ks++) {
                unsigned af[4];
                ldsm4(af, a_u + 2u * ((wm * 16 + (lane & 15)) * 104
                                      + ks * 16 + ((lane >> 4) << 3)));
                #pragma unroll
                for (int np = 0; np < 3; np++) {
                    unsigned bf[4];
                    ldsmB(bf, w_s + (wn * 48 + np * 16) * 104 + ks * 16, 104, lane);
                    mma16(acc[np * 2], af, bf);
                    mma16(acc[np * 2 + 1], af, bf + 2);
                }
            }
            __nv_bfloat16* hc = h_s + ph * (64 * 104);
            #pragma unroll
            for (int nt = 0; nt < 6; nt++) {
                int cc = wn * 48 + nt * 8 + tig * 2;
                float bb0 = fb1[ph * 96 + cc], bb1 = fb1[ph * 96 + cc + 1];
                #pragma unroll
                for (int half = 0; half < 2; half++) {
                    int rl = wm * 16 + gid + half * 8;
                    *(unsigned*)(hc + rl * 104 + cc) =
                        pack2(gelu_exact(acc[nt][half * 2 + 0] + bb0),
                              gelu_exact(acc[nt][half * 2 + 1] + bb1));
                }
            }
        } else {
            int kc = ph - 4;
            if (kc == 0) {
                #pragma unroll
                for (int nt = 0; nt < 6; nt++)
                    #pragma unroll
                    for (int e = 0; e < 4; e++) acc[nt][e] = 0.f;
            }
            unsigned hc_u = h_u + 2u * kc * (64 * 104);
            #pragma unroll
            for (int ks = 0; ks < 6; ks++) {
                unsigned af[4];
                ldsm4(af, hc_u + 2u * ((wm * 16 + (lane & 15)) * 104
                                       + ks * 16 + ((lane >> 4) << 3)));
                #pragma unroll
                for (int np = 0; np < 3; np++) {
                    unsigned bf[4];
                    ldsmB(bf, w_s + (wn * 48 + np * 16) * 104 + ks * 16, 104, lane);
                    mma16(acc[np * 2], af, bf);
                    mma16(acc[np * 2 + 1], af, bf + 2);
                }
            }
        }
    }
    #pragma unroll
    for (int nt = 0; nt < 6; nt++) {
        int cc = wn * 48 + nt * 8 + tig * 2;
        float bb0 = fb2[cc], bb1 = fb2[cc + 1];
        #pragma unroll
        for (int half = 0; half < 2; half++) {
            int r = m0 + wm * 16 + gid + half * 8;
            size_t idx = (size_t)r * 96 + cc;
            float2 r1 = *(const float2*)(x1 + idx);
            float2 o2;
            o2.x = r1.x + acc[nt][half * 2 + 0] + bb0;
            o2.y = r1.y + acc[nt][half * 2 + 1] + bb1;
            *(float2*)(out + idx) = o2;
        }
    }
}

// ---------------- proj GEMM + residual merge + fused LayerNorm2 ----------------
__global__ __launch_bounds__(256) void gemm_proj_ln(
    const __nv_bfloat16* __restrict__ A, const __nv_bfloat16* __restrict__ Wt,
    const float* __restrict__ bias,
    const float* __restrict__ res1, const __nv_bfloat16* __restrict__ res2,
    const float* __restrict__ att,
    const float* __restrict__ n2g, const float* __restrict__ n2b,
    float* __restrict__ x1, __nv_bfloat16* __restrict__ xn2)
{
    extern __shared__ __nv_bfloat16 smb[];
    __nv_bfloat16* a_s = smb;
    __nv_bfloat16* w_s = smb + 128 * 104;
    float* red_s = (float*)smb;
    float* red_q = red_s + 256;
    unsigned a_u = (unsigned)__cvta_generic_to_shared(a_s);
    int m0 = blockIdx.x * 128;
    int tx = threadIdx.x;
    int warp = tx >> 5, lane = tx & 31;
    int wm = warp >> 1, wn = warp & 1;
    int gid = lane >> 2, tig = lane & 3;
    float acc[2][6][4] = {};
    {
        for (int idx = tx; idx < 1536; idx += 256) {
            int r = idx / 12, c = idx - r * 12;
            *(uint4*)(a_s + r * 104 + c * 8) = *(const uint4*)(A + (size_t)(m0 + r) * 96 + c * 8);
        }
        for (int idx = tx; idx < 1152; idx += 256) {
            int r = idx / 12, c = idx - r * 12;
            *(uint4*)(w_s + r * 104 + c * 8) = *(const uint4*)(Wt + (size_t)r * 96 + c * 8);
        }
        __syncthreads();
        #pragma unroll
        for (int ks = 0; ks < 6; ks++) {
            unsigned af[2][4];
            #pragma unroll
            for (int mt = 0; mt < 2; mt++)
                ldsm4(af[mt], a_u + 2u * ((wm * 32 + mt * 16 + (lane & 15)) * 104
                                          + ks * 16 + ((lane >> 4) << 3)));
            #pragma unroll
            for (int np = 0; np < 3; np++) {
                unsigned bf[4];
                ldsmB(bf, w_s + (wn * 48 + np * 16) * 104 + ks * 16, 104, lane);
                #pragma unroll
                for (int mt = 0; mt < 2; mt++) {
                    mma16(acc[mt][np * 2], af[mt], bf);
                    mma16(acc[mt][np * 2 + 1], af[mt], bf + 2);
                }
            }
        }
    }
    __syncthreads();

    float rs[2][2] = {}, rq[2][2] = {};
    #pragma unroll
    for (int mt = 0; mt < 2; mt++) {
        #pragma unroll
        for (int nt = 0; nt < 6; nt++) {
            int cc = wn * 48 + nt * 8 + tig * 2;
            float bb0 = bias[cc], bb1 = bias[cc + 1];
            float a0 = att[cc] * 0.01f, a1 = att[cc + 1] * 0.01f;
            #pragma unroll
            for (int half = 0; half < 2; half++) {
                int r = m0 + wm * 32 + mt * 16 + gid + half * 8;
                size_t idx = (size_t)r * 96 + cc;
                float2 r1 = *(const float2*)(res1 + idx);
                float2 r2 = __bfloat1622float2(*(const __nv_bfloat162*)(res2 + idx));
                float v0 = r1.x + acc[mt][nt][half * 2 + 0] + bb0 + r2.x * a0;
                float v1 = r1.y + acc[mt][nt][half * 2 + 1] + bb1 + r2.y * a1;
                acc[mt][nt][half * 2 + 0] = v0;
                acc[mt][nt][half * 2 + 1] = v1;
                *(float2*)(x1 + idx) = make_float2(v0, v1);
                rs[mt][half] += v0 + v1;
                rq[mt][half] += v0 * v0 + v1 * v1;
            }
        }
    }
    #pragma unroll
    for (int mt = 0; mt < 2; mt++)
        #pragma unroll
        for (int half = 0; half < 2; half++) {
            float s = rs[mt][half], q = rq[mt][half];
            s += __shfl_xor_sync(0xffffffffu, s, 1);
            s += __shfl_xor_sync(0xffffffffu, s, 2);
            q += __shfl_xor_sync(0xffffffffu, q, 1);
            q += __shfl_xor_sync(0xffffffffu, q, 2);
            if (tig == 0) {
                int lr = wm * 32 + mt * 16 + half * 8 + gid;
                red_s[lr * 2 + wn] = s;
                red_q[lr * 2 + wn] = q;
            }
        }
    __syncthreads();
    #pragma unroll
    for (int mt = 0; mt < 2; mt++) {
        #pragma unroll
        for (int half = 0; half < 2; half++) {
            int lr = wm * 32 + mt * 16 + half * 8 + gid;
            float sum = red_s[lr * 2] + red_s[lr * 2 + 1];
            float sq  = red_q[lr * 2] + red_q[lr * 2 + 1];
            float mean = sum * (1.0f / 96.0f);
            float var = sq * (1.0f / 96.0f) - mean * mean;
            float inv = rsqrtf(var + 1e-5f);
            int r = m0 + lr;
            #pragma unroll
            for (int nt = 0; nt < 6; nt++) {
                int cc = wn * 48 + nt * 8 + tig * 2;
                float g0 = n2g[cc], g1 = n2g[cc + 1];
                float b0 = n2b[cc], b1 = n2b[cc + 1];
                float v0 = (acc[mt][nt][half * 2 + 0] - mean) * inv * g0 + b0;
                float v1 = (acc[mt][nt][half * 2 + 1] - mean) * inv * g1 + b1;
                *(unsigned*)(xn2 + (size_t)r * 96 + cc) = pack2(v0, v1);
            }
        }
    }
}

// ---------------- attention (window-ordered qkv input) ----------------
#define OFF_Q  0
#define OFF_K  3072
#define OFF_V  27648
#define OFF_R1 44288
#define OFF_R2 45312
#define OFF_OR 46336
#define SMEM_ATTN 62720

__device__ __forceinline__ int wtok(int j, int base) {
    return ((j >> 6) << 12) + base + (((j >> 3) & 7) << 6) + (j & 7);
}

__global__ __launch_bounds__(512) void attn_kernel(
    const __nv_bfloat16* __restrict__ qkv, const __nv_bfloat16* __restrict__ biasb,
    __nv_bfloat16* __restrict__ o)
{
    extern __shared__ char smc[];
    __nv_bfloat16* q_s = (__nv_bfloat16*)(smc + OFF_Q);
    __nv_bfloat16* k_s = (__nv_bfloat16*)(smc + OFF_K);
    __nv_bfloat16* v_t = (__nv_bfloat16*)(smc + OFF_V);
    float* red1 = (float*)(smc + OFF_R1);
    float* red2 = (float*)(smc + OFF_R2);
    float* o_red = (float*)(smc + OFF_OR);
    unsigned q_u = (unsigned)__cvta_generic_to_shared(q_s);

    int blk = blockIdx.x;
    int qc = blk & 7;
    int head = (blk >> 3) % 6;
    int win = blk / 48;
    int base = (win >> 3) * 512 + (win & 7) * 8;
    int m0 = qc * 64;
    int tx = threadIdx.x;
    int warp = tx >> 5, lane = tx & 31;
    int gid = lane >> 2, tig = lane & 3;
    int wm = warp >> 2, wn = warp & 3;
    int r0 = wm * 16, j0 = wn * 128;

    const __nv_bfloat16* qbase = qkv + ((size_t)((win) * 6 + head) << 13);
    const __nv_bfloat16* kbase = qkv + ((size_t)(((64 + win)) * 6 + head) << 13);
    const __nv_bfloat16* vbase = qkv + ((size_t)(((128 + win)) * 6 + head) << 13);

    for (int idx = tx; idx < 1024; idx += 512) {
        int j = idx >> 1, half = idx & 1;
        *(uint4*)(k_s + j * 24 + half * 8) = *(const uint4*)(kbase + j * 16 + half * 8);
        uint4 v4 = *(const uint4*)(vbase + j * 16 + half * 8);
        const __nv_bfloat16* vp = (const __nv_bfloat16*)&v4;
        #pragma unroll
        for (int dd2 = 0; dd2 < 8; dd2++)
            v_t[(half * 8 + dd2) * 520 + j] = vp[dd2];
    }
    if (tx < 128) {
        int i = tx >> 1, half = tx & 1;
        uint4 raw = *(const uint4*)(qbase + (m0 + i) * 16 + half * 8);
        const __nv_bfloat16* rp = (const __nv_bfloat16*)&raw;
        unsigned pk[4];
        #pragma unroll
        for (int e = 0; e < 4; e++)
            pk[e] = pack2(__bfloat162float(rp[e * 2]) * 0.25f,
                          __bfloat162float(rp[e * 2 + 1]) * 0.25f);
        *(uint4*)(q_s + i * 24 + half * 8) = *(uint4*)pk;
    }
    __syncthreads();

    float acc[16][4] = {};
    {
        unsigned aq[4];
        ldsm4(aq, q_u + 2u * ((r0 + (lane & 15)) * 24 + ((lane >> 4) << 3)));
        #pragma unroll
        for (int np = 0; np < 8; np++) {
            unsigned bf[4];
            ldsmB(bf, k_s + (j0 + np * 16) * 24, 24, lane);
            mma16(acc[np * 2], aq, bf);
            mma16(acc[np * 2 + 1], aq, bf + 2);
        }
        const __nv_bfloat16* bbA = biasb + ((size_t)head * 512 + (m0 + r0 + gid)) * 512 + j0 + tig * 2;
        const __nv_bfloat16* bbB = bbA + 8 * 512;
        #pragma unroll
        for (int nt = 0; nt < 16; nt++) {
            float2 fa = __bfloat1622float2(*(const __nv_bfloat162*)(bbA + nt * 8));
            float2 fb = __bfloat1622float2(*(const __nv_bfloat162*)(bbB + nt * 8));
            acc[nt][0] += fa.x; acc[nt][1] += fa.y;
            acc[nt][2] += fb.x; acc[nt][3] += fb.y;
        }
    }
    {
        float mA = -1e30f, mB = -1e30f;
        #pragma unroll
        for (int nt = 0; nt < 16; nt++) {
            mA = fmaxf(mA, fmaxf(acc[nt][0], acc[nt][1]));
            mB = fmaxf(mB, fmaxf(acc[nt][2], acc[nt][3]));
        }
        mA = fmaxf(mA, __shfl_xor_sync(0xffffffffu, mA, 1));
        mA = fmaxf(mA, __shfl_xor_sync(0xffffffffu, mA, 2));
        mB = fmaxf(mB, __shfl_xor_sync(0xffffffffu, mB, 1));
        mB = fmaxf(mB, __shfl_xor_sync(0xffffffffu, mB, 2));
        if (tig == 0) {
            red1[(r0 + gid) * 4 + wn] = mA;
            red1[(r0 + gid + 8) * 4 + wn] = mB;
        }
        __syncthreads();
        mA = fmaxf(fmaxf(red1[(r0 + gid) * 4 + 0], red1[(r0 + gid) * 4 + 1]),
                   fmaxf(red1[(r0 + gid) * 4 + 2], red1[(r0 + gid) * 4 + 3]));
        mB = fmaxf(fmaxf(red1[(r0 + gid + 8) * 4 + 0], red1[(r0 + gid + 8) * 4 + 1]),
                   fmaxf(red1[(r0 + gid + 8) * 4 + 2], red1[(r0 + gid + 8) * 4 + 3]));
        float sA = 0.f, sB = 0.f;
        #pragma unroll
        for (int nt = 0; nt < 16; nt++) {
            acc[nt][0] = __expf(acc[nt][0] - mA);
            acc[nt][1] = __expf(acc[nt][1] - mA);
            acc[nt][2] = __expf(acc[nt][2] - mB);
            acc[nt][3] = __expf(acc[nt][3] - mB);
            sA += acc[nt][0] + acc[nt][1];
            sB += acc[nt][2] + acc[nt][3];
        }
        sA += __shfl_xor_sync(0xffffffffu, sA, 1);
        sA += __shfl_xor_sync(0xffffffffu, sA, 2);
        sB += __shfl_xor_sync(0xffffffffu, sB, 1);
        sB += __shfl_xor_sync(0xffffffffu, sB, 2);
        if (tig == 0) {
            red2[(r0 + gid) * 4 + wn] = sA;
            red2[(r0 + gid + 8) * 4 + wn] = sB;
        }
        __syncthreads();
        sA = red2[(r0 + gid) * 4 + 0] + red2[(r0 + gid) * 4 + 1]
           + red2[(r0 + gid) * 4 + 2] + red2[(r0 + gid) * 4 + 3];
        sB = red2[(r0 + gid + 8) * 4 + 0] + red2[(r0 + gid + 8) * 4 + 1]
           + red2[(r0 + gid + 8) * 4 + 2] + red2[(r0 + gid + 8) * 4 + 3];
        float iA = 1.0f / sA, iB = 1.0f / sB;
        #pragma unroll
        for (int nt = 0; nt < 16; nt++) {
            acc[nt][0] *= iA; acc[nt][1] *= iA;
            acc[nt][2] *= iB; acc[nt][3] *= iB;
        }
    }

    float oa[2][4] = {};
    #pragma unroll
    for (int kk = 0; kk < 8; kk++) {
        unsigned af[4];
        af[0] = pack2(acc[2 * kk][0],     acc[2 * kk][1]);
        af[1] = pack2(acc[2 * kk][2],     acc[2 * kk][3]);
        af[2] = pack2(acc[2 * kk + 1][0], acc[2 * kk + 1][1]);
        af[3] = pack2(acc[2 * kk + 1][2], acc[2 * kk + 1][3]);
        unsigned bf[4];
        ldsmB(bf, v_t + j0 + kk * 16, 520, lane);
        mma16(oa[0], af, bf);
        mma16(oa[1], af, bf + 2);
    }
    {
        float* orp = o_red + (size_t)wn * 1024;
        #pragma unroll
        for (int dt = 0; dt < 2; dt++) {
            int dc = dt * 8 + tig * 2;
            *(float2*)(orp + (r0 + gid) * 16 + dc)     = make_float2(oa[dt][0], oa[dt][1]);
            *(float2*)(orp + (r0 + gid + 8) * 16 + dc) = make_float2(oa[dt][2], oa[dt][3]);
        }
    }
    __syncthreads();
    {
        int row = tx >> 3, d2 = tx & 7;
        int dim = d2 * 2;
        float v0 = 0.f, v1 = 0.f;
        #pragma unroll
        for (int p = 0; p < 4; p++) {
            v0 += o_red[p * 1024 + row * 16 + dim];
            v1 += o_red[p * 1024 + row * 16 + dim + 1];
        }
        int t = wtok(m0 + row, base);
        *(unsigned*)(o + (size_t)t * CCH + head * 16 + dim) = pack2(v0, v1);
    }
}

// ---------------- launch ----------------
extern "C" void kernel_launch(void* const* d_in, const int* in_sizes, int n_in,
                              void* d_out, int out_size)
{
    (void)in_sizes; (void)n_in; (void)out_size;
    const float* x       = (const float*)d_in[0];
    const float* n1g     = (const float*)d_in[1];
    const float* n1b     = (const float*)d_in[2];
    const float* qkv_w   = (const float*)d_in[3];
    const float* qkv_b   = (const float*)d_in[4];
    const float* rpbt    = (const float*)d_in[5];
    const float* proj_w  = (const float*)d_in[6];
    const float* proj_b  = (const float*)d_in[7];
    const float* conv1_w = (const float*)d_in[8];
    const float* conv1_b = (const float*)d_in[9];
    const float* conv2_w = (const float*)d_in[10];
    const float* conv2_b = (const float*)d_in[11];
    const float* ca1_w   = (const float*)d_in[12];
    const float* ca1_b   = (const float*)d_in[13];
    const float* ca2_w   = (const float*)d_in[14];
    const float* ca2_b   = (const float*)d_in[15];
    const float* n2g     = (const float*)d_in[16];
    const float* n2b     = (const float*)d_in[17];
    const float* fc1_w   = (const float*)d_in[18];
    const float* fc1_b   = (const float*)d_in[19];
    const float* fc2_w   = (const float*)d_in[20];
    const float* fc2_b   = (const float*)d_in[21];
    const int*   rpi     = (const int*)d_in[22];
    float* out = (float*)d_out;

    __nv_bfloat16 *xn, *y1, *y2, *qkvb, *biasb, *ob, *xn2, *w1r, *w2r, *qw, *pw, *f1w, *f2w;
    float *part, *att, *x1;
    cudaGetSymbolAddress((void**)&xn,    g_xn);
    cudaGetSymbolAddress((void**)&y1,    g_y1);
    cudaGetSymbolAddress((void**)&y2,    g_y2);
    cudaGetSymbolAddress((void**)&part,  g_part);
    cudaGetSymbolAddress((void**)&att,   g_att);
    cudaGetSymbolAddress((void**)&qkvb,  g_qkv);
    cudaGetSymbolAddress((void**)&biasb, g_bias);
    cudaGetSymbolAddress((void**)&ob,    g_o);
    cudaGetSymbolAddress((void**)&x1,    g_x1);
    cudaGetSymbolAddress((void**)&xn2,   g_xn2);
    cudaGetSymbolAddress((void**)&w1r,   g_w1r);
    cudaGetSymbolAddress((void**)&w2r,   g_w2r);
    cudaGetSymbolAddress((void**)&qw,    g_qw);
    cudaGetSymbolAddress((void**)&pw,    g_pw);
    cudaGetSymbolAddress((void**)&f1w,   g_f1w);
    cudaGetSymbolAddress((void**)&f2w,   g_f2w);

    const int SMEM_CONV1 = 2 * C1_SE * 2;
    const int SMEM_CONV2 = 2 * C2_SE * 2;
    const int SMEM_G128  = (128 + 96) * 104 * 2;
    const int SMEM_QKV   = QKV_XS * 2 + 128 * 96 * 4;   // 95744
    const int SMEM_MLP   = MLP_SE * 2;

    static bool s_init = false;
    static cudaStream_t sW, sC;
    static cudaEvent_t eFork, eW, eConv;
    if (!s_init) {
        cudaStreamCreateWithFlags(&sW, cudaStreamNonBlocking);
        cudaStreamCreateWithFlags(&sC, cudaStreamNonBlocking);
        cudaEventCreateWithFlags(&eFork, cudaEventDisableTiming);
        cudaEventCreateWithFlags(&eW,    cudaEventDisableTiming);
        cudaEventCreateWithFlags(&eConv, cudaEventDisableTiming);
        cudaFuncSetAttribute(conv1_kernel, cudaFuncAttributeMaxDynamicSharedMemorySize, SMEM_CONV1);
        cudaFuncSetAttribute(conv2_kernel, cudaFuncAttributeMaxDynamicSharedMemorySize, SMEM_CONV2);
        cudaFuncSetAttribute(gemm_qkv_ln, cudaFuncAttributeMaxDynamicSharedMemorySize, SMEM_QKV);
        cudaFuncSetAttribute(gemm_proj_ln, cudaFuncAttributeMaxDynamicSharedMemorySize, SMEM_G128);
        cudaFuncSetAttribute(mlp_kernel, cudaFuncAttributeMaxDynamicSharedMemorySize, SMEM_MLP);
        cudaFuncSetAttribute(attn_kernel, cudaFuncAttributeMaxDynamicSharedMemorySize, SMEM_ATTN);
        s_init = true;
    }

    cudaEventRecord(eFork, 0);

    // stream W: weight conversions
    cudaStreamWaitEvent(sW, eFork, 0);
    setup_w_kernel<<<1080, 256, 0, sW>>>(qkv_w, proj_w, fc1_w, fc2_w, conv1_w, conv2_w,
                                         qw, pw, f1w, f2w, w1r, w2r);
    cudaEventRecord(eW, sW);

    // stream C: ln (for conv branch) -> conv branch
    cudaStreamWaitEvent(sC, eFork, 0);
    ln_kernel<<<LTOK / 8, 256, 0, sC>>>(x, n1g, n1b, xn);
    cudaStreamWaitEvent(sC, eW, 0);
    conv1_kernel<<<512, 256, SMEM_CONV1, sC>>>(xn, w1r, conv1_b, y1);
    conv2_kernel<<<512, 256, SMEM_CONV2, sC>>>(y1, w2r, conv2_b, y2, part);
    ca_kernel<<<1, CCH, 0, sC>>>(part, ca1_w, ca1_b, ca2_w, ca2_b, att);
    cudaEventRecord(eConv, sC);

    // origin: bias expansion (overlaps), then fused LN+qkv -> attn
    setup_bias_kernel<<<3072, 256>>>(rpi, rpbt, biasb);
    cudaStreamWaitEvent(0, eW, 0);
    gemm_qkv_ln<<<dim3(LTOK / 128, 3), 256, SMEM_QKV>>>(x, n1g, n1b, qw, qkv_b, qkvb);
    attn_kernel<<<NWIN * HEADS * 8, 512, SMEM_ATTN>>>(qkvb, biasb, ob);

    cudaStreamWaitEvent(0, eConv, 0);
    gemm_proj_ln<<<LTOK / 128, 256, SMEM_G128>>>(
        ob, pw, proj_b, x, y2, att, n2g, n2b, x1, xn2);
    mlp_kernel<<<LTOK / 64, 256, SMEM_MLP>>>(xn2, f1w, fc1_b, f2w, fc2_b, x1, out);
}

// round 15
// speedup vs baseline: 1.0211x; 1.0211x over previous
#include <cuda_runtime.h>
#include <cuda_bf16.h>
#include <math.h>
#include <stdint.h>

#define DD 8
#define HH 64
#define WW 64
#define LTOK 32768
#define CCH 96
#define CMP 32
#define HID 384
#define HEADS 6
#define HDIM 16
#define NWIN 64
#define NTOK 512

// ---------------- scratch ----------------
__device__ __nv_bfloat16 g_xn  [LTOK * CCH];
__device__ __nv_bfloat16 g_y1  [LTOK * CMP];
__device__ __nv_bfloat16 g_y2  [LTOK * CCH];
__device__ float         g_part[512 * CCH];
__device__ float         g_att [CCH];
__device__ __nv_bfloat16 g_qkv [LTOK * 3 * CCH];
__device__ __nv_bfloat16 g_bias[HEADS * NTOK * NTOK];
__device__ __nv_bfloat16 g_o   [LTOK * CCH];
__device__ float         g_x1  [LTOK * CCH];
__device__ __nv_bfloat16 g_xn2 [LTOK * CCH];
__device__ __nv_bfloat16 g_w1r [27 * CMP * CCH];
__device__ __nv_bfloat16 g_w2r [27 * CCH * CMP];
__device__ __nv_bfloat16 g_qw  [288 * 96];
__device__ __nv_bfloat16 g_pw  [96 * 96];
__device__ __nv_bfloat16 g_f1w [384 * 96];
__device__ __nv_bfloat16 g_f2w [96 * 384];

__device__ __forceinline__ float gelu_exact(float v) {
    return 0.5f * v * (1.0f + erff(v * 0.70710678118654752f));
}
__device__ __forceinline__ unsigned pack2(float a, float b) {
    __nv_bfloat162 t = __floats2bfloat162_rn(a, b);
    return *reinterpret_cast<unsigned*>(&t);
}
__device__ __forceinline__ void ldsm4(unsigned* r, unsigned addr) {
    asm volatile("ldmatrix.sync.aligned.m8n8.x4.shared.b16 {%0,%1,%2,%3},[%4];"
                 : "=r"(r[0]), "=r"(r[1]), "=r"(r[2]), "=r"(r[3]) : "r"(addr));
}
__device__ __forceinline__ void ldsmB(unsigned* r, const __nv_bfloat16* base, int S, int lane) {
    int tq = lane & 7, sel = lane >> 3;
    const __nv_bfloat16* p = base + ((sel & 2) * 4 + tq) * S + (sel & 1) * 8;
    ldsm4(r, (unsigned)__cvta_generic_to_shared(p));
}
__device__ __forceinline__ void mma16(float* d, const unsigned* a, const unsigned* b) {
    asm volatile(
        "mma.sync.aligned.m16n8k16.row.col.f32.bf16.bf16.f32 "
        "{%0,%1,%2,%3},{%4,%5,%6,%7},{%8,%9},{%0,%1,%2,%3};"
        : "+f"(d[0]), "+f"(d[1]), "+f"(d[2]), "+f"(d[3])
        : "r"(a[0]), "r"(a[1]), "r"(a[2]), "r"(a[3]), "r"(b[0]), "r"(b[1]));
}
__device__ __forceinline__ void cpa16(__nv_bfloat16* s, const void* g, bool v) {
    unsigned sa = (unsigned)__cvta_generic_to_shared(s);
    int sz = v ? 16 : 0;
    asm volatile("cp.async.cg.shared.global [%0], [%1], 16, %2;" :: "r"(sa), "l"(g), "r"(sz));
}
__device__ __forceinline__ void cpa_commit() { asm volatile("cp.async.commit_group;"); }
template <int N> __device__ __forceinline__ void cpa_wait() {
    asm volatile("cp.async.wait_group %0;" :: "n"(N));
}

// ---------------- LayerNorm ----------------
__global__ void ln_kernel(const float* __restrict__ x, const float* __restrict__ g,
                          const float* __restrict__ b, __nv_bfloat16* __restrict__ out)
{
    int row  = blockIdx.x * 8 + (threadIdx.x >> 5);
    int lane = threadIdx.x & 31;
    const float* xr = x + (size_t)row * CCH;
    float v0 = xr[lane], v1 = xr[lane + 32], v2 = xr[lane + 64];
    float s = v0 + v1 + v2;
    #pragma unroll
    for (int o = 16; o; o >>= 1) s += __shfl_xor_sync(0xffffffffu, s, o);
    float mu = s * (1.0f / 96.0f);
    float d0 = v0 - mu, d1 = v1 - mu, d2 = v2 - mu;
    float q = d0 * d0 + d1 * d1 + d2 * d2;
    #pragma unroll
    for (int o = 16; o; o >>= 1) q += __shfl_xor_sync(0xffffffffu, q, o);
    float inv = rsqrtf(q * (1.0f / 96.0f) + 1e-5f);
    __nv_bfloat16* orow = out + (size_t)row * CCH;
    orow[lane]      = __float2bfloat16(d0 * inv * g[lane]      + b[lane]);
    orow[lane + 32] = __float2bfloat16(d1 * inv * g[lane + 32] + b[lane + 32]);
    orow[lane + 64] = __float2bfloat16(d2 * inv * g[lane + 64] + b[lane + 64]);
}

// ---------------- setup: weights only (1080 blocks) ----------------
__global__ void setup_w_kernel(
    const float* __restrict__ qkv_w, const float* __restrict__ proj_w,
    const float* __restrict__ fc1_w, const float* __restrict__ fc2_w,
    const float* __restrict__ conv1_w, const float* __restrict__ conv2_w,
    __nv_bfloat16* __restrict__ qw, __nv_bfloat16* __restrict__ pw,
    __nv_bfloat16* __restrict__ f1w, __nv_bfloat16* __restrict__ f2w,
    __nv_bfloat16* __restrict__ w1r, __nv_bfloat16* __restrict__ w2r)
{
    int b = blockIdx.x, tx = threadIdx.x;
    if (b < 108) {
        int i = b * 256 + tx;
        if (i < 288 * 96) qw[i] = __float2bfloat16(qkv_w[i]);
    } else if (b < 144) {
        int i = (b - 108) * 256 + tx;
        if (i < 96 * 96) pw[i] = __float2bfloat16(proj_w[i]);
    } else if (b < 288) {
        int i = (b - 144) * 256 + tx;
        if (i < 384 * 96) f1w[i] = __float2bfloat16(fc1_w[i]);
    } else if (b < 432) {
        int i = (b - 288) * 256 + tx;
        if (i < 96 * 384) f2w[i] = __float2bfloat16(fc2_w[i]);
    } else if (b < 756) {
        int tid = (b - 432) * 256 + tx;
        if (tid < CMP * CCH * 27) {
            int o = tid / (CCH * 27);
            int rem = tid - o * (CCH * 27);
            int c = rem / 27;
            int tap = rem - c * 27;
            w1r[(tap * CMP + o) * CCH + c] = __float2bfloat16(conv1_w[tid]);
        }
    } else {
        int tid = (b - 756) * 256 + tx;
        if (tid < CCH * CMP * 27) {
            int o = tid / (CMP * 27);
            int rem = tid - o * (CMP * 27);
            int i = rem / 27;
            int tap = rem - i * 27;
            w2r[(tap * CCH + o) * CMP + i] = __float2bfloat16(conv2_w[tid]);
        }
    }
}

// ---------------- setup: bias expansion ----------------
__global__ void setup_bias_kernel(const int* __restrict__ rpi, const float* __restrict__ rpbt,
                                  __nv_bfloat16* __restrict__ biasb)
{
    int tid = blockIdx.x * 256 + threadIdx.x;
    int e = tid * 2;
    int h = e >> 18;
    int r = e & 262143;
    int2 ri = *(const int2*)(rpi + r);
    *(unsigned*)(biasb + e) = pack2(rpbt[ri.x * HEADS + h], rpbt[ri.y * HEADS + h]);
}

// ---------------- conv1: 96->32 + GELU, 2-stage cp.async ----------------
#define C1_SE (162 * 104)
__global__ __launch_bounds__(256) void conv1_kernel(
    const __nv_bfloat16* __restrict__ xn, const __nv_bfloat16* __restrict__ w1r,
    const float* __restrict__ b1, __nv_bfloat16* __restrict__ y1)
{
    extern __shared__ __nv_bfloat16 smb[];
    int d = blockIdx.x >> 6, h = blockIdx.x & 63;
    int tx = threadIdx.x;
    int warp = tx >> 5, lane = tx & 31;
    int gid = lane >> 2, tig = lane & 3;
    int wm = warp >> 1, wn = warp & 1;
    float acc[2][4] = {};

    auto load_phase = [&](int p, int buf) {
        int kd = p / 3, kh = p - kd * 3;
        int dd = d + kd - 1, hh = h + kh - 1;
        bool rowv = ((unsigned)dd < 8u) && ((unsigned)hh < 64u);
        __nv_bfloat16* in_s = smb + buf * C1_SE;
        __nv_bfloat16* w_s  = in_s + 66 * 104;
        const __nv_bfloat16* src_row = xn + ((size_t)(dd * HH + hh) * WW) * CCH;
        for (int idx = tx; idx < 792; idx += 256) {
            int r = idx / 12, c = idx - r * 12;
            int wv = r - 1;
            bool v = rowv && (unsigned)wv < 64u;
            const void* g = v ? (const void*)(src_row + wv * CCH + c * 8) : (const void*)xn;
            cpa16(in_s + r * 104 + c * 8, g, v);
        }
        const __nv_bfloat16* wsrc = w1r + (size_t)p * 3 * (CMP * CCH);
        for (int idx = tx; idx < 1152; idx += 256) {
            int r = idx / 12, c = idx - r * 12;
            cpa16(w_s + r * 104 + c * 8, wsrc + idx * 8, true);
        }
        cpa_commit();
    };

    load_phase(0, 0);
    for (int p = 0; p < 9; p++) {
        cpa_wait<0>();
        __syncthreads();
        if (p < 8) load_phase(p + 1, (p + 1) & 1);
        __nv_bfloat16* in_s = smb + (p & 1) * C1_SE;
        __nv_bfloat16* w_s  = in_s + 66 * 104;
        unsigned in_u = (unsigned)__cvta_generic_to_shared(in_s);
        #pragma unroll
        for (int kw = 0; kw < 3; kw++) {
            #pragma unroll
            for (int ks = 0; ks < 6; ks++) {
                unsigned af[4];
                ldsm4(af, in_u + 2u * ((wm * 16 + kw + (lane & 15)) * 104
                                       + ks * 16 + ((lane >> 4) << 3)));
                unsigned bf[4];
                ldsmB(bf, w_s + (kw * 32 + wn * 16) * 104 + ks * 16, 104, lane);
                mma16(acc[0], af, bf);
                mma16(acc[1], af, bf + 2);
            }
        }
    }
    __nv_bfloat16* orow = y1 + (size_t)(d * HH + h) * WW * CMP;
    #pragma unroll
    for (int nt = 0; nt < 2; nt++) {
        int oc = wn * 16 + nt * 8 + tig * 2;
        float bb0 = b1[oc], bb1 = b1[oc + 1];
        #pragma unroll
        for (int half = 0; half < 2; half++) {
            int v = wm * 16 + gid + half * 8;
            *(unsigned*)(orow + v * CMP + oc) =
                pack2(gelu_exact(acc[nt][half * 2 + 0] + bb0),
                      gelu_exact(acc[nt][half * 2 + 1] + bb1));
        }
    }
}

// ---------------- conv2: 32->96, 2-stage cp.async + fused pool partials ----------------
#define C2_SE (354 * 40)
__global__ __launch_bounds__(256) void conv2_kernel(
    const __nv_bfloat16* __restrict__ y1, const __nv_bfloat16* __restrict__ w2r,
    const float* __restrict__ b2, __nv_bfloat16* __restrict__ y2, float* __restrict__ part)
{
    extern __shared__ __nv_bfloat16 smb[];
    int d = blockIdx.x >> 6, h = blockIdx.x & 63;
    int tx = threadIdx.x;
    int warp = tx >> 5, lane = tx & 31;
    int gid = lane >> 2, tig = lane & 3;
    int wm = warp >> 1, wn = warp & 1;
    float acc[6][4] = {};

    auto load_phase = [&](int p, int buf) {
        int kd = p / 3, kh = p - kd * 3;
        int dd = d + kd - 1, hh = h + kh - 1;
        bool rowv = ((unsigned)dd < 8u) && ((unsigned)hh < 64u);
        __nv_bfloat16* in_s = smb + buf * C2_SE;
        __nv_bfloat16* w_s  = in_s + 66 * 40;
        const __nv_bfloat16* src_row = y1 + ((size_t)(dd * HH + hh) * WW) * CMP;
        for (int idx = tx; idx < 264; idx += 256) {
            int r = idx >> 2, c = idx & 3;
            int wv = r - 1;
            bool v = rowv && (unsigned)wv < 64u;
            const void* g = v ? (const void*)(src_row + wv * CMP + c * 8) : (const void*)y1;
            cpa16(in_s + r * 40 + c * 8, g, v);
        }
        const __nv_bfloat16* wsrc = w2r + (size_t)p * 3 * (CCH * CMP);
        for (int idx = tx; idx < 1152; idx += 256) {
            int r = idx >> 2, c = idx & 3;
            cpa16(w_s + r * 40 + c * 8, wsrc + idx * 8, true);
        }
        cpa_commit();
    };

    load_phase(0, 0);
    for (int p = 0; p < 9; p++) {
        cpa_wait<0>();
        __syncthreads();
        if (p < 8) load_phase(p + 1, (p + 1) & 1);
        __nv_bfloat16* in_s = smb + (p & 1) * C2_SE;
        __nv_bfloat16* w_s  = in_s + 66 * 40;
        unsigned in_u = (unsigned)__cvta_generic_to_shared(in_s);
        #pragma unroll
        for (int kw = 0; kw < 3; kw++) {
            #pragma unroll
            for (int ks = 0; ks < 2; ks++) {
                unsigned af[4];
                ldsm4(af, in_u + 2u * ((wm * 16 + kw + (lane & 15)) * 40
                                       + ks * 16 + ((lane >> 4) << 3)));
                #pragma unroll
                for (int np = 0; np < 3; np++) {
                    unsigned bf[4];
                    ldsmB(bf, w_s + (kw * 96 + wn * 48 + np * 16) * 40 + ks * 16, 40, lane);
                    mma16(acc[np * 2], af, bf);
                    mma16(acc[np * 2 + 1], af, bf + 2);
                }
            }
        }
    }
    __nv_bfloat16* orow = y2 + (size_t)(d * HH + h) * WW * CCH;
    float ch0[6], ch1[6];
    #pragma unroll
    for (int nt = 0; nt < 6; nt++) {
        int oc = wn * 48 + nt * 8 + tig * 2;
        float bb0 = b2[oc], bb1 = b2[oc + 1];
        #pragma unroll
        for (int half = 0; half < 2; half++) {
            int v = wm * 16 + gid + half * 8;
            *(unsigned*)(orow + v * CCH + oc) =
                pack2(acc[nt][half * 2 + 0] + bb0, acc[nt][half * 2 + 1] + bb1);
        }
        ch0[nt] = acc[nt][0] + acc[nt][2] + 2.0f * bb0;
        ch1[nt] = acc[nt][1] + acc[nt][3] + 2.0f * bb1;
    }
    #pragma unroll
    for (int nt = 0; nt < 6; nt++) {
        #pragma unroll
        for (int m = 4; m < 32; m <<= 1) {
            ch0[nt] += __shfl_xor_sync(0xffffffffu, ch0[nt], m);
            ch1[nt] += __shfl_xor_sync(0xffffffffu, ch1[nt], m);
        }
    }
    __syncthreads();
    float* ws = (float*)smb;
    if (gid == 0) {
        #pragma unroll
        for (int nt = 0; nt < 6; nt++) {
            int oc = wn * 48 + nt * 8 + tig * 2;
            ws[warp * 96 + oc] = ch0[nt];
            ws[warp * 96 + oc + 1] = ch1[nt];
        }
    }
    __syncthreads();
    if (tx < 96) {
        int wn2 = tx / 48;
        float s = ws[wn2 * 96 + tx] + ws[(wn2 + 2) * 96 + tx]
                + ws[(wn2 + 4) * 96 + tx] + ws[(wn2 + 6) * 96 + tx];
        part[blockIdx.x * 96 + tx] = s;
    }
}

// ---------------- channel attention ----------------
__global__ void ca_kernel(const float* __restrict__ part,
                          const float* __restrict__ ca1w, const float* __restrict__ ca1b,
                          const float* __restrict__ ca2w, const float* __restrict__ ca2b,
                          float* __restrict__ att)
{
    __shared__ float p[CCH], hs[3];
    int tx = threadIdx.x;
    float s = 0.f;
    for (int b = 0; b < 512; b++) s += part[b * CCH + tx];
    p[tx] = s * (1.0f / (float)LTOK);
    __syncthreads();
    if (tx < 3) {
        float a = ca1b[tx];
        for (int c = 0; c < CCH; c++) a += ca1w[tx * CCH + c] * p[c];
        hs[tx] = fmaxf(a, 0.f);
    }
    __syncthreads();
    float a = ca2b[tx];
    #pragma unroll
    for (int k = 0; k < 3; k++) a += ca2w[tx * 3 + k] * hs[k];
    att[tx] = 1.0f / (1.0f + expf(-a));
}

// ---------------- qkv GEMM (128-row tile, K=96, bf16 out) ----------------
__global__ __launch_bounds__(256) void gemm_qkv(
    const __nv_bfloat16* __restrict__ A, const __nv_bfloat16* __restrict__ Wt,
    const float* __restrict__ bias, __nv_bfloat16* __restrict__ Cout, int Nn)
{
    extern __shared__ __nv_bfloat16 smb[];
    int m0 = blockIdx.x * 128, n0 = blockIdx.y * 96;
    int tx = threadIdx.x;
    int warp = tx >> 5, lane = tx & 31;
    int wm = warp >> 1, wn = warp & 1;
    int gid = lane >> 2, tig = lane & 3;
    float acc[2][6][4] = {};
    for (int idx = tx; idx < 1536; idx += 256) {
        int r = idx / 12, c = idx - r * 12;
        *(uint4*)(smb + r * 104 + c * 8) = *(const uint4*)(A + (size_t)(m0 + r) * 96 + c * 8);
    }
    for (int idx = tx; idx < 1152; idx += 256) {
        int r = idx / 12, c = idx - r * 12;
        *(uint4*)(smb + (128 + r) * 104 + c * 8) = *(const uint4*)(Wt + (size_t)(n0 + r) * 96 + c * 8);
    }
    __syncthreads();
    __nv_bfloat16* w_s = smb + 128 * 104;
    unsigned a_u = (unsigned)__cvta_generic_to_shared(smb);
    #pragma unroll
    for (int ks = 0; ks < 6; ks++) {
        unsigned af[2][4];
        #pragma unroll
        for (int mt = 0; mt < 2; mt++)
            ldsm4(af[mt], a_u + 2u * ((wm * 32 + mt * 16 + (lane & 15)) * 104
                                      + ks * 16 + ((lane >> 4) << 3)));
        #pragma unroll
        for (int np = 0; np < 3; np++) {
            unsigned bf[4];
            ldsmB(bf, w_s + (wn * 48 + np * 16) * 104 + ks * 16, 104, lane);
            #pragma unroll
            for (int mt = 0; mt < 2; mt++) {
                mma16(acc[mt][np * 2], af[mt], bf);
                mma16(acc[mt][np * 2 + 1], af[mt], bf + 2);
            }
        }
    }
    #pragma unroll
    for (int mt = 0; mt < 2; mt++) {
        #pragma unroll
        for (int nt = 0; nt < 6; nt++) {
            int cc = n0 + wn * 48 + nt * 8 + tig * 2;
            float bb0 = bias[cc], bb1 = bias[cc + 1];
            #pragma unroll
            for (int half = 0; half < 2; half++) {
                int r = m0 + wm * 32 + mt * 16 + gid + half * 8;
                size_t idx = (size_t)r * Nn + cc;
                *(unsigned*)(Cout + idx) = pack2(acc[mt][nt][half * 2 + 0] + bb0,
                                                 acc[mt][nt][half * 2 + 1] + bb1);
            }
        }
    }
}

// ---------------- fused MLP: out = x1 + gelu(xn2@f1w+b1)@f2w + b2 ----------------
#define MLP_A  0
#define MLP_W  (64 * 104)
#define MLP_H  (MLP_W + 2 * 96 * 104)
#define MLP_SE (MLP_H + 4 * 64 * 104)
__global__ __launch_bounds__(256) void mlp_kernel(
    const __nv_bfloat16* __restrict__ xn2, const __nv_bfloat16* __restrict__ f1w,
    const float* __restrict__ fb1, const __nv_bfloat16* __restrict__ f2w,
    const float* __restrict__ fb2, const float* __restrict__ x1,
    float* __restrict__ out)
{
    extern __shared__ __nv_bfloat16 smb[];
    __nv_bfloat16* a_s = smb + MLP_A;
    __nv_bfloat16* h_s = smb + MLP_H;
    int m0 = blockIdx.x * 64;
    int tx = threadIdx.x;
    int warp = tx >> 5, lane = tx & 31;
    int wm = warp >> 1, wn = warp & 1;
    int gid = lane >> 2, tig = lane & 3;

    for (int idx = tx; idx < 768; idx += 256) {
        int r = idx / 12, c = idx - r * 12;
        *(uint4*)(a_s + r * 104 + c * 8) = *(const uint4*)(xn2 + (size_t)(m0 + r) * 96 + c * 8);
    }
    auto load_w = [&](int ph, int buf) {
        __nv_bfloat16* w_s = smb + MLP_W + buf * (96 * 104);
        const __nv_bfloat16* src = (ph < 4)
            ? f1w + (size_t)(ph * 96) * 96
            : f2w + (size_t)(ph - 4) * 96;
        size_t rstride = (ph < 4) ? 96 : 384;
        for (int idx = tx; idx < 1152; idx += 256) {
            int r = idx / 12, c = idx - r * 12;
            cpa16(w_s + r * 104 + c * 8, src + (size_t)r * rstride + c * 8, true);
        }
        cpa_commit();
    };
    load_w(0, 0);

    float acc[6][4] = {};
    unsigned a_u = (unsigned)__cvta_generic_to_shared(a_s);
    unsigned h_u = (unsigned)__cvta_generic_to_shared(h_s);

    for (int ph = 0; ph < 8; ph++) {
        cpa_wait<0>();
        __syncthreads();
        if (ph < 7) load_w(ph + 1, (ph + 1) & 1);
        __nv_bfloat16* w_s = smb + MLP_W + (ph & 1) * (96 * 104);
        if (ph < 4) {
            #pragma unroll
            for (int nt = 0; nt < 6; nt++)
                #pragma unroll
                for (int e = 0; e < 4; e++) acc[nt][e] = 0.f;
            #pragma unroll
            for (int ks = 0; ks < 6; ks++) {
                unsigned af[4];
                ldsm4(af, a_u + 2u * ((wm * 16 + (lane & 15)) * 104
                                      + ks * 16 + ((lane >> 4) << 3)));
                #pragma unroll
                for (int np = 0; np < 3; np++) {
                    unsigned bf[4];
                    ldsmB(bf, w_s + (wn * 48 + np * 16) * 104 + ks * 16, 104, lane);
                    mma16(acc[np * 2], af, bf);
                    mma16(acc[np * 2 + 1], af, bf + 2);
                }
            }
            __nv_bfloat16* hc = h_s + ph * (64 * 104);
            #pragma unroll
            for (int nt = 0; nt < 6; nt++) {
                int cc = wn * 48 + nt * 8 + tig * 2;
                float bb0 = fb1[ph * 96 + cc], bb1 = fb1[ph * 96 + cc + 1];
                #pragma unroll
                for (int half = 0; half < 2; half++) {
                    int rl = wm * 16 + gid + half * 8;
                    *(unsigned*)(hc + rl * 104 + cc) =
                        pack2(gelu_exact(acc[nt][half * 2 + 0] + bb0),
                              gelu_exact(acc[nt][half * 2 + 1] + bb1));
                }
            }
        } else {
            int kc = ph - 4;
            if (kc == 0) {
                #pragma unroll
                for (int nt = 0; nt < 6; nt++)
                    #pragma unroll
                    for (int e = 0; e < 4; e++) acc[nt][e] = 0.f;
            }
            unsigned hc_u = h_u + 2u * kc * (64 * 104);
            #pragma unroll
            for (int ks = 0; ks < 6; ks++) {
                unsigned af[4];
                ldsm4(af, hc_u + 2u * ((wm * 16 + (lane & 15)) * 104
                                       + ks * 16 + ((lane >> 4) << 3)));
                #pragma unroll
                for (int np = 0; np < 3; np++) {
                    unsigned bf[4];
                    ldsmB(bf, w_s + (wn * 48 + np * 16) * 104 + ks * 16, 104, lane);
                    mma16(acc[np * 2], af, bf);
                    mma16(acc[np * 2 + 1], af, bf + 2);
                }
            }
        }
    }
    #pragma unroll
    for (int nt = 0; nt < 6; nt++) {
        int cc = wn * 48 + nt * 8 + tig * 2;
        float bb0 = fb2[cc], bb1 = fb2[cc + 1];
        #pragma unroll
        for (int half = 0; half < 2; half++) {
            int r = m0 + wm * 16 + gid + half * 8;
            size_t idx = (size_t)r * 96 + cc;
            float2 r1 = *(const float2*)(x1 + idx);
            float2 o2;
            o2.x = r1.x + acc[nt][half * 2 + 0] + bb0;
            o2.y = r1.y + acc[nt][half * 2 + 1] + bb1;
            *(float2*)(out + idx) = o2;
        }
    }
}

// ---------------- proj GEMM + residual merge + fused LayerNorm2 ----------------
__global__ __launch_bounds__(256) void gemm_proj_ln(
    const __nv_bfloat16* __restrict__ A, const __nv_bfloat16* __restrict__ Wt,
    const float* __restrict__ bias,
    const float* __restrict__ res1, const __nv_bfloat16* __restrict__ res2,
    const float* __restrict__ att,
    const float* __restrict__ n2g, const float* __restrict__ n2b,
    float* __restrict__ x1, __nv_bfloat16* __restrict__ xn2)
{
    extern __shared__ __nv_bfloat16 smb[];
    __nv_bfloat16* a_s = smb;
    __nv_bfloat16* w_s = smb + 128 * 104;
    float* red_s = (float*)smb;
    float* red_q = red_s + 256;
    unsigned a_u = (unsigned)__cvta_generic_to_shared(a_s);
    int m0 = blockIdx.x * 128;
    int tx = threadIdx.x;
    int warp = tx >> 5, lane = tx & 31;
    int wm = warp >> 1, wn = warp & 1;
    int gid = lane >> 2, tig = lane & 3;
    float acc[2][6][4] = {};
    {
        for (int idx = tx; idx < 1536; idx += 256) {
            int r = idx / 12, c = idx - r * 12;
            *(uint4*)(a_s + r * 104 + c * 8) = *(const uint4*)(A + (size_t)(m0 + r) * 96 + c * 8);
        }
        for (int idx = tx; idx < 1152; idx += 256) {
            int r = idx / 12, c = idx - r * 12;
            *(uint4*)(w_s + r * 104 + c * 8) = *(const uint4*)(Wt + (size_t)r * 96 + c * 8);
        }
        __syncthreads();
        #pragma unroll
        for (int ks = 0; ks < 6; ks++) {
            unsigned af[2][4];
            #pragma unroll
            for (int mt = 0; mt < 2; mt++)
                ldsm4(af[mt], a_u + 2u * ((wm * 32 + mt * 16 + (lane & 15)) * 104
                                          + ks * 16 + ((lane >> 4) << 3)));
            #pragma unroll
            for (int np = 0; np < 3; np++) {
                unsigned bf[4];
                ldsmB(bf, w_s + (wn * 48 + np * 16) * 104 + ks * 16, 104, lane);
                #pragma unroll
                for (int mt = 0; mt < 2; mt++) {
                    mma16(acc[mt][np * 2], af[mt], bf);
                    mma16(acc[mt][np * 2 + 1], af[mt], bf + 2);
                }
            }
        }
    }
    __syncthreads();

    float rs[2][2] = {}, rq[2][2] = {};
    #pragma unroll
    for (int mt = 0; mt < 2; mt++) {
        #pragma unroll
        for (int nt = 0; nt < 6; nt++) {
            int cc = wn * 48 + nt * 8 + tig * 2;
            float bb0 = bias[cc], bb1 = bias[cc + 1];
            float a0 = att[cc] * 0.01f, a1 = att[cc + 1] * 0.01f;
            #pragma unroll
            for (int half = 0; half < 2; half++) {
                int r = m0 + wm * 32 + mt * 16 + gid + half * 8;
                size_t idx = (size_t)r * 96 + cc;
                float2 r1 = *(const float2*)(res1 + idx);
                float2 r2 = __bfloat1622float2(*(const __nv_bfloat162*)(res2 + idx));
                float v0 = r1.x + acc[mt][nt][half * 2 + 0] + bb0 + r2.x * a0;
                float v1 = r1.y + acc[mt][nt][half * 2 + 1] + bb1 + r2.y * a1;
                acc[mt][nt][half * 2 + 0] = v0;
                acc[mt][nt][half * 2 + 1] = v1;
                *(float2*)(x1 + idx) = make_float2(v0, v1);
                rs[mt][half] += v0 + v1;
                rq[mt][half] += v0 * v0 + v1 * v1;
            }
        }
    }
    #pragma unroll
    for (int mt = 0; mt < 2; mt++)
        #pragma unroll
        for (int half = 0; half < 2; half++) {
            float s = rs[mt][half], q = rq[mt][half];
            s += __shfl_xor_sync(0xffffffffu, s, 1);
            s += __shfl_xor_sync(0xffffffffu, s, 2);
            q += __shfl_xor_sync(0xffffffffu, q, 1);
            q += __shfl_xor_sync(0xffffffffu, q, 2);
            if (tig == 0) {
                int lr = wm * 32 + mt * 16 + half * 8 + gid;
                red_s[lr * 2 + wn] = s;
                red_q[lr * 2 + wn] = q;
            }
        }
    __syncthreads();
    #pragma unroll
    for (int mt = 0; mt < 2; mt++) {
        #pragma unroll
        for (int half = 0; half < 2; half++) {
            int lr = wm * 32 + mt * 16 + half * 8 + gid;
            float sum = red_s[lr * 2] + red_s[lr * 2 + 1];
            float sq  = red_q[lr * 2] + red_q[lr * 2 + 1];
            float mean = sum * (1.0f / 96.0f);
            float var = sq * (1.0f / 96.0f) - mean * mean;
            float inv = rsqrtf(var + 1e-5f);
            int r = m0 + lr;
            #pragma unroll
            for (int nt = 0; nt < 6; nt++) {
                int cc = wn * 48 + nt * 8 + tig * 2;
                float g0 = n2g[cc], g1 = n2g[cc + 1];
                float b0 = n2b[cc], b1 = n2b[cc + 1];
                float v0 = (acc[mt][nt][half * 2 + 0] - mean) * inv * g0 + b0;
                float v1 = (acc[mt][nt][half * 2 + 1] - mean) * inv * g1 + b1;
                *(unsigned*)(xn2 + (size_t)r * 96 + cc) = pack2(v0, v1);
            }
        }
    }
}

// ---------------- attention ----------------
#define OFF_Q  0
#define OFF_K  3072
#define OFF_V  27648
#define OFF_R1 44288
#define OFF_R2 45312
#define OFF_OR 46336
#define SMEM_ATTN 62720

__device__ __forceinline__ int wtok(int j, int base) {
    return ((j >> 6) << 12) + base + (((j >> 3) & 7) << 6) + (j & 7);
}

__global__ __launch_bounds__(512) void attn_kernel(
    const __nv_bfloat16* __restrict__ qkv, const __nv_bfloat16* __restrict__ biasb,
    __nv_bfloat16* __restrict__ o)
{
    extern __shared__ char smc[];
    __nv_bfloat16* q_s = (__nv_bfloat16*)(smc + OFF_Q);
    __nv_bfloat16* k_s = (__nv_bfloat16*)(smc + OFF_K);
    __nv_bfloat16* v_t = (__nv_bfloat16*)(smc + OFF_V);
    float* red1 = (float*)(smc + OFF_R1);
    float* red2 = (float*)(smc + OFF_R2);
    float* o_red = (float*)(smc + OFF_OR);
    unsigned q_u = (unsigned)__cvta_generic_to_shared(q_s);

    int blk = blockIdx.x;
    int qc = blk & 7;
    int head = (blk >> 3) % 6;
    int win = blk / 48;
    int base = (win >> 3) * 512 + (win & 7) * 8;
    int m0 = qc * 64;
    int tx = threadIdx.x;
    int warp = tx >> 5, lane = tx & 31;
    int gid = lane >> 2, tig = lane & 3;
    int wm = warp >> 2, wn = warp & 3;
    int r0 = wm * 16, j0 = wn * 128;

    for (int idx = tx; idx < 1024; idx += 512) {
        int j = idx >> 1, half = idx & 1;
        int t = wtok(j, base);
        const __nv_bfloat16* p = qkv + (size_t)t * 288 + head * 16 + half * 8;
        *(uint4*)(k_s + j * 24 + half * 8) = *(const uint4*)(p + 96);
        uint4 v4 = *(const uint4*)(p + 192);
        const __nv_bfloat16* vp = (const __nv_bfloat16*)&v4;
        #pragma unroll
        for (int dd2 = 0; dd2 < 8; dd2++)
            v_t[(half * 8 + dd2) * 520 + j] = vp[dd2];
    }
    if (tx < 128) {
        int i = tx >> 1, half = tx & 1;
        int t = wtok(m0 + i, base);
        uint4 raw = *(const uint4*)(qkv + (size_t)t * 288 + head * 16 + half * 8);
        const __nv_bfloat16* rp = (const __nv_bfloat16*)&raw;
        unsigned pk[4];
        #pragma unroll
        for (int e = 0; e < 4; e++)
            pk[e] = pack2(__bfloat162float(rp[e * 2]) * 0.25f,
                          __bfloat162float(rp[e * 2 + 1]) * 0.25f);
        *(uint4*)(q_s + i * 24 + half * 8) = *(uint4*)pk;
    }
    __syncthreads();

    float acc[16][4] = {};
    {
        unsigned aq[4];
        ldsm4(aq, q_u + 2u * ((r0 + (lane & 15)) * 24 + ((lane >> 4) << 3)));
        #pragma unroll
        for (int np = 0; np < 8; np++) {
            unsigned bf[4];
            ldsmB(bf, k_s + (j0 + np * 16) * 24, 24, lane);
            mma16(acc[np * 2], aq, bf);
            mma16(acc[np * 2 + 1], aq, bf + 2);
        }
        const __nv_bfloat16* bbA = biasb + ((size_t)head * 512 + (m0 + r0 + gid)) * 512 + j0 + tig * 2;
        const __nv_bfloat16* bbB = bbA + 8 * 512;
        #pragma unroll
        for (int nt = 0; nt < 16; nt++) {
            float2 fa = __bfloat1622float2(*(const __nv_bfloat162*)(bbA + nt * 8));
            float2 fb = __bfloat1622float2(*(const __nv_bfloat162*)(bbB + nt * 8));
            acc[nt][0] += fa.x; acc[nt][1] += fa.y;
            acc[nt][2] += fb.x; acc[nt][3] += fb.y;
        }
    }
    {
        float mA = -1e30f, mB = -1e30f;
        #pragma unroll
        for (int nt = 0; nt < 16; nt++) {
            mA = fmaxf(mA, fmaxf(acc[nt][0], acc[nt][1]));
            mB = fmaxf(mB, fmaxf(acc[nt][2], acc[nt][3]));
        }
        mA = fmaxf(mA, __shfl_xor_sync(0xffffffffu, mA, 1));
        mA = fmaxf(mA, __shfl_xor_sync(0xffffffffu, mA, 2));
        mB = fmaxf(mB, __shfl_xor_sync(0xffffffffu, mB, 1));
        mB = fmaxf(mB, __shfl_xor_sync(0xffffffffu, mB, 2));
        if (tig == 0) {
            red1[(r0 + gid) * 4 + wn] = mA;
            red1[(r0 + gid + 8) * 4 + wn] = mB;
        }
        __syncthreads();
        mA = fmaxf(fmaxf(red1[(r0 + gid) * 4 + 0], red1[(r0 + gid) * 4 + 1]),
                   fmaxf(red1[(r0 + gid) * 4 + 2], red1[(r0 + gid) * 4 + 3]));
        mB = fmaxf(fmaxf(red1[(r0 + gid + 8) * 4 + 0], red1[(r0 + gid + 8) * 4 + 1]),
                   fmaxf(red1[(r0 + gid + 8) * 4 + 2], red1[(r0 + gid + 8) * 4 + 3]));
        float sA = 0.f, sB = 0.f;
        #pragma unroll
        for (int nt = 0; nt < 16; nt++) {
            acc[nt][0] = __expf(acc[nt][0] - mA);
            acc[nt][1] = __expf(acc[nt][1] - mA);
            acc[nt][2] = __expf(acc[nt][2] - mB);
            acc[nt][3] = __expf(acc[nt][3] - mB);
            sA += acc[nt][0] + acc[nt][1];
            sB += acc[nt][2] + acc[nt][3];
        }
        sA += __shfl_xor_sync(0xffffffffu, sA, 1);
        sA += __shfl_xor_sync(0xffffffffu, sA, 2);
        sB += __shfl_xor_sync(0xffffffffu, sB, 1);
        sB += __shfl_xor_sync(0xffffffffu, sB, 2);
        if (tig == 0) {
            red2[(r0 + gid) * 4 + wn] = sA;
            red2[(r0 + gid + 8) * 4 + wn] = sB;
        }
        __syncthreads();
        sA = red2[(r0 + gid) * 4 + 0] + red2[(r0 + gid) * 4 + 1]
           + red2[(r0 + gid) * 4 + 2] + red2[(r0 + gid) * 4 + 3];
        sB = red2[(r0 + gid + 8) * 4 + 0] + red2[(r0 + gid + 8) * 4 + 1]
           + red2[(r0 + gid + 8) * 4 + 2] + red2[(r0 + gid + 8) * 4 + 3];
        float iA = 1.0f / sA, iB = 1.0f / sB;
        #pragma unroll
        for (int nt = 0; nt < 16; nt++) {
            acc[nt][0] *= iA; acc[nt][1] *= iA;
            acc[nt][2] *= iB; acc[nt][3] *= iB;
        }
    }

    float oa[2][4] = {};
    #pragma unroll
    for (int kk = 0; kk < 8; kk++) {
        unsigned af[4];
        af[0] = pack2(acc[2 * kk][0],     acc[2 * kk][1]);
        af[1] = pack2(acc[2 * kk][2],     acc[2 * kk][3]);
        af[2] = pack2(acc[2 * kk + 1][0], acc[2 * kk + 1][1]);
        af[3] = pack2(acc[2 * kk + 1][2], acc[2 * kk + 1][3]);
        unsigned bf[4];
        ldsmB(bf, v_t + j0 + kk * 16, 520, lane);
        mma16(oa[0], af, bf);
        mma16(oa[1], af, bf + 2);
    }
    {
        float* orp = o_red + (size_t)wn * 1024;
        #pragma unroll
        for (int dt = 0; dt < 2; dt++) {
            int dc = dt * 8 + tig * 2;
            *(float2*)(orp + (r0 + gid) * 16 + dc)     = make_float2(oa[dt][0], oa[dt][1]);
            *(float2*)(orp + (r0 + gid + 8) * 16 + dc) = make_float2(oa[dt][2], oa[dt][3]);
        }
    }
    __syncthreads();
    {
        int row = tx >> 3, d2 = tx & 7;
        int dim = d2 * 2;
        float v0 = 0.f, v1 = 0.f;
        #pragma unroll
        for (int p = 0; p < 4; p++) {
            v0 += o_red[p * 1024 + row * 16 + dim];
            v1 += o_red[p * 1024 + row * 16 + dim + 1];
        }
        int t = wtok(m0 + row, base);
        *(unsigned*)(o + (size_t)t * CCH + head * 16 + dim) = pack2(v0, v1);
    }
}

// ---------------- launch ----------------
extern "C" void kernel_launch(void* const* d_in, const int* in_sizes, int n_in,
                              void* d_out, int out_size)
{
    (void)in_sizes; (void)n_in; (void)out_size;
    const float* x       = (const float*)d_in[0];
    const float* n1g     = (const float*)d_in[1];
    const float* n1b     = (const float*)d_in[2];
    const float* qkv_w   = (const float*)d_in[3];
    const float* qkv_b   = (const float*)d_in[4];
    const float* rpbt    = (const float*)d_in[5];
    const float* proj_w  = (const float*)d_in[6];
    const float* proj_b  = (const float*)d_in[7];
    const float* conv1_w = (const float*)d_in[8];
    const float* conv1_b = (const float*)d_in[9];
    const float* conv2_w = (const float*)d_in[10];
    const float* conv2_b = (const float*)d_in[11];
    const float* ca1_w   = (const float*)d_in[12];
    const float* ca1_b   = (const float*)d_in[13];
    const float* ca2_w   = (const float*)d_in[14];
    const float* ca2_b   = (const float*)d_in[15];
    const float* n2g     = (const float*)d_in[16];
    const float* n2b     = (const float*)d_in[17];
    const float* fc1_w   = (const float*)d_in[18];
    const float* fc1_b   = (const float*)d_in[19];
    const float* fc2_w   = (const float*)d_in[20];
    const float* fc2_b   = (const float*)d_in[21];
    const int*   rpi     = (const int*)d_in[22];
    float* out = (float*)d_out;

    __nv_bfloat16 *xn, *y1, *y2, *qkvb, *biasb, *ob, *xn2, *w1r, *w2r, *qw, *pw, *f1w, *f2w;
    float *part, *att, *x1;
    cudaGetSymbolAddress((void**)&xn,    g_xn);
    cudaGetSymbolAddress((void**)&y1,    g_y1);
    cudaGetSymbolAddress((void**)&y2,    g_y2);
    cudaGetSymbolAddress((void**)&part,  g_part);
    cudaGetSymbolAddress((void**)&att,   g_att);
    cudaGetSymbolAddress((void**)&qkvb,  g_qkv);
    cudaGetSymbolAddress((void**)&biasb, g_bias);
    cudaGetSymbolAddress((void**)&ob,    g_o);
    cudaGetSymbolAddress((void**)&x1,    g_x1);
    cudaGetSymbolAddress((void**)&xn2,   g_xn2);
    cudaGetSymbolAddress((void**)&w1r,   g_w1r);
    cudaGetSymbolAddress((void**)&w2r,   g_w2r);
    cudaGetSymbolAddress((void**)&qw,    g_qw);
    cudaGetSymbolAddress((void**)&pw,    g_pw);
    cudaGetSymbolAddress((void**)&f1w,   g_f1w);
    cudaGetSymbolAddress((void**)&f2w,   g_f2w);

    const int SMEM_CONV1 = 2 * C1_SE * 2;
    const int SMEM_CONV2 = 2 * C2_SE * 2;
    const int SMEM_G128  = (128 + 96) * 104 * 2;
    const int SMEM_MLP   = MLP_SE * 2;

    static bool s_init = false;
    static cudaStream_t sW, sC;
    static cudaEvent_t eFork, eLn, eW, eBias, eConv;
    if (!s_init) {
        cudaStreamCreateWithFlags(&sW, cudaStreamNonBlocking);
        cudaStreamCreateWithFlags(&sC, cudaStreamNonBlocking);
        cudaEventCreateWithFlags(&eFork, cudaEventDisableTiming);
        cudaEventCreateWithFlags(&eLn,   cudaEventDisableTiming);
        cudaEventCreateWithFlags(&eW,    cudaEventDisableTiming);
        cudaEventCreateWithFlags(&eBias, cudaEventDisableTiming);
        cudaEventCreateWithFlags(&eConv, cudaEventDisableTiming);
        cudaFuncSetAttribute(conv1_kernel, cudaFuncAttributeMaxDynamicSharedMemorySize, SMEM_CONV1);
        cudaFuncSetAttribute(conv2_kernel, cudaFuncAttributeMaxDynamicSharedMemorySize, SMEM_CONV2);
        cudaFuncSetAttribute(gemm_qkv, cudaFuncAttributeMaxDynamicSharedMemorySize, SMEM_G128);
        cudaFuncSetAttribute(gemm_proj_ln, cudaFuncAttributeMaxDynamicSharedMemorySize, SMEM_G128);
        cudaFuncSetAttribute(mlp_kernel, cudaFuncAttributeMaxDynamicSharedMemorySize, SMEM_MLP);
        cudaFuncSetAttribute(attn_kernel, cudaFuncAttributeMaxDynamicSharedMemorySize, SMEM_ATTN);
        s_init = true;
    }

    cudaEventRecord(eFork, 0);

    // stream W: weight conversions, then bias expansion (both off critical path)
    cudaStreamWaitEvent(sW, eFork, 0);
    setup_w_kernel<<<1080, 256, 0, sW>>>(qkv_w, proj_w, fc1_w, fc2_w, conv1_w, conv2_w,
                                         qw, pw, f1w, f2w, w1r, w2r);
    cudaEventRecord(eW, sW);
    setup_bias_kernel<<<3072, 256, 0, sW>>>(rpi, rpbt, biasb);
    cudaEventRecord(eBias, sW);

    // origin: LN1
    ln_kernel<<<LTOK / 8, 256>>>(x, n1g, n1b, xn);
    cudaEventRecord(eLn, 0);

    // stream C: conv branch
    cudaStreamWaitEvent(sC, eLn, 0);
    cudaStreamWaitEvent(sC, eW, 0);
    conv1_kernel<<<512, 256, SMEM_CONV1, sC>>>(xn, w1r, conv1_b, y1);
    conv2_kernel<<<512, 256, SMEM_CONV2, sC>>>(y1, w2r, conv2_b, y2, part);
    ca_kernel<<<1, CCH, 0, sC>>>(part, ca1_w, ca1_b, ca2_w, ca2_b, att);
    cudaEventRecord(eConv, sC);

    // origin: attention branch
    cudaStreamWaitEvent(0, eW, 0);
    gemm_qkv<<<dim3(LTOK / 128, 3), 256, SMEM_G128>>>(xn, qw, qkv_b, qkvb, 288);
    cudaStreamWaitEvent(0, eBias, 0);
    attn_kernel<<<NWIN * HEADS * 8, 512, SMEM_ATTN>>>(qkvb, biasb, ob);

    cudaStreamWaitEvent(0, eConv, 0);
    gemm_proj_ln<<<LTOK / 128, 256, SMEM_G128>>>(
        ob, pw, proj_b, x, y2, att, n2g, n2b, x1, xn2);
    mlp_kernel<<<LTOK / 64, 256, SMEM_MLP>>>(xn2, f1w, fc1_b, f2w, fc2_b, x1, out);
}

// round 16
// speedup vs baseline: 1.0654x; 1.0434x over previous
#include <cuda_runtime.h>
#include <cuda_bf16.h>
#include <math.h>
#include <stdint.h>

#define DD 8
#define HH 64
#define WW 64
#define LTOK 32768
#define CCH 96
#define CMP 32
#define HID 384
#define HEADS 6
#define HDIM 16
#define NWIN 64
#define NTOK 512

// ---------------- scratch ----------------
__device__ __nv_bfloat16 g_xn  [LTOK * CCH];
__device__ __nv_bfloat16 g_y1  [LTOK * CMP];
__device__ __nv_bfloat16 g_y2  [LTOK * CCH];
__device__ float         g_part[512 * CCH];
__device__ float         g_att [CCH];
__device__ __nv_bfloat16 g_qkv [LTOK * 3 * CCH];
__device__ __nv_bfloat16 g_bias[HEADS * NTOK * NTOK];
__device__ __nv_bfloat16 g_o   [LTOK * CCH];
__device__ float         g_x1  [LTOK * CCH];
__device__ __nv_bfloat16 g_xn2 [LTOK * CCH];
__device__ __nv_bfloat16 g_w1r [27 * CMP * CCH];
__device__ __nv_bfloat16 g_w2r [27 * CCH * CMP];
__device__ __nv_bfloat16 g_qw  [288 * 96];
__device__ __nv_bfloat16 g_pw  [96 * 96];
__device__ __nv_bfloat16 g_f1w [384 * 96];
__device__ __nv_bfloat16 g_f2w [96 * 384];

__device__ __forceinline__ float gelu_exact(float v) {
    return 0.5f * v * (1.0f + erff(v * 0.70710678118654752f));
}
__device__ __forceinline__ unsigned pack2(float a, float b) {
    __nv_bfloat162 t = __floats2bfloat162_rn(a, b);
    return *reinterpret_cast<unsigned*>(&t);
}
__device__ __forceinline__ void ldsm4(unsigned* r, unsigned addr) {
    asm volatile("ldmatrix.sync.aligned.m8n8.x4.shared.b16 {%0,%1,%2,%3},[%4];"
                 : "=r"(r[0]), "=r"(r[1]), "=r"(r[2]), "=r"(r[3]) : "r"(addr));
}
__device__ __forceinline__ void ldsmB(unsigned* r, const __nv_bfloat16* base, int S, int lane) {
    int tq = lane & 7, sel = lane >> 3;
    const __nv_bfloat16* p = base + ((sel & 2) * 4 + tq) * S + (sel & 1) * 8;
    ldsm4(r, (unsigned)__cvta_generic_to_shared(p));
}
__device__ __forceinline__ void mma16(float* d, const unsigned* a, const unsigned* b) {
    asm volatile(
        "mma.sync.aligned.m16n8k16.row.col.f32.bf16.bf16.f32 "
        "{%0,%1,%2,%3},{%4,%5,%6,%7},{%8,%9},{%0,%1,%2,%3};"
        : "+f"(d[0]), "+f"(d[1]), "+f"(d[2]), "+f"(d[3])
        : "r"(a[0]), "r"(a[1]), "r"(a[2]), "r"(a[3]), "r"(b[0]), "r"(b[1]));
}
__device__ __forceinline__ void cpa16(__nv_bfloat16* s, const void* g, bool v) {
    unsigned sa = (unsigned)__cvta_generic_to_shared(s);
    int sz = v ? 16 : 0;
    asm volatile("cp.async.cg.shared.global [%0], [%1], 16, %2;" :: "r"(sa), "l"(g), "r"(sz));
}
__device__ __forceinline__ void cpa_commit() { asm volatile("cp.async.commit_group;"); }
template <int N> __device__ __forceinline__ void cpa_wait() {
    asm volatile("cp.async.wait_group %0;" :: "n"(N));
}

// ---------------- LayerNorm ----------------
__global__ void ln_kernel(const float* __restrict__ x, const float* __restrict__ g,
                          const float* __restrict__ b, __nv_bfloat16* __restrict__ out)
{
    int row  = blockIdx.x * 8 + (threadIdx.x >> 5);
    int lane = threadIdx.x & 31;
    const float* xr = x + (size_t)row * CCH;
    float v0 = xr[lane], v1 = xr[lane + 32], v2 = xr[lane + 64];
    float s = v0 + v1 + v2;
    #pragma unroll
    for (int o = 16; o; o >>= 1) s += __shfl_xor_sync(0xffffffffu, s, o);
    float mu = s * (1.0f / 96.0f);
    float d0 = v0 - mu, d1 = v1 - mu, d2 = v2 - mu;
    float q = d0 * d0 + d1 * d1 + d2 * d2;
    #pragma unroll
    for (int o = 16; o; o >>= 1) q += __shfl_xor_sync(0xffffffffu, q, o);
    float inv = rsqrtf(q * (1.0f / 96.0f) + 1e-5f);
    __nv_bfloat16* orow = out + (size_t)row * CCH;
    orow[lane]      = __float2bfloat16(d0 * inv * g[lane]      + b[lane]);
    orow[lane + 32] = __float2bfloat16(d1 * inv * g[lane + 32] + b[lane + 32]);
    orow[lane + 64] = __float2bfloat16(d2 * inv * g[lane + 64] + b[lane + 64]);
}

// ---------------- setup: weights only (1080 blocks) ----------------
__global__ void setup_w_kernel(
    const float* __restrict__ qkv_w, const float* __restrict__ proj_w,
    const float* __restrict__ fc1_w, const float* __restrict__ fc2_w,
    const float* __restrict__ conv1_w, const float* __restrict__ conv2_w,
    __nv_bfloat16* __restrict__ qw, __nv_bfloat16* __restrict__ pw,
    __nv_bfloat16* __restrict__ f1w, __nv_bfloat16* __restrict__ f2w,
    __nv_bfloat16* __restrict__ w1r, __nv_bfloat16* __restrict__ w2r)
{
    int b = blockIdx.x, tx = threadIdx.x;
    if (b < 108) {
        int i = b * 256 + tx;
        if (i < 288 * 96) qw[i] = __float2bfloat16(qkv_w[i]);
    } else if (b < 144) {
        int i = (b - 108) * 256 + tx;
        if (i < 96 * 96) pw[i] = __float2bfloat16(proj_w[i]);
    } else if (b < 288) {
        int i = (b - 144) * 256 + tx;
        if (i < 384 * 96) f1w[i] = __float2bfloat16(fc1_w[i]);
    } else if (b < 432) {
        int i = (b - 288) * 256 + tx;
        if (i < 96 * 384) f2w[i] = __float2bfloat16(fc2_w[i]);
    } else if (b < 756) {
        int tid = (b - 432) * 256 + tx;
        if (tid < CMP * CCH * 27) {
            int o = tid / (CCH * 27);
            int rem = tid - o * (CCH * 27);
            int c = rem / 27;
            int tap = rem - c * 27;
            w1r[(tap * CMP + o) * CCH + c] = __float2bfloat16(conv1_w[tid]);
        }
    } else {
        int tid = (b - 756) * 256 + tx;
        if (tid < CCH * CMP * 27) {
            int o = tid / (CMP * 27);
            int rem = tid - o * (CMP * 27);
            int i = rem / 27;
            int tap = rem - i * 27;
            w2r[(tap * CCH + o) * CMP + i] = __float2bfloat16(conv2_w[tid]);
        }
    }
}

// ---------------- setup: bias expansion ----------------
__global__ void setup_bias_kernel(const int* __restrict__ rpi, const float* __restrict__ rpbt,
                                  __nv_bfloat16* __restrict__ biasb)
{
    int tid = blockIdx.x * 256 + threadIdx.x;
    int e = tid * 2;
    int h = e >> 18;
    int r = e & 262143;
    int2 ri = *(const int2*)(rpi + r);
    *(unsigned*)(biasb + e) = pack2(rpbt[ri.x * HEADS + h], rpbt[ri.y * HEADS + h]);
}

// ---------------- conv1: 96->32 + GELU, 2-stage cp.async ----------------
#define C1_SE (162 * 104)
__global__ __launch_bounds__(256) void conv1_kernel(
    const __nv_bfloat16* __restrict__ xn, const __nv_bfloat16* __restrict__ w1r,
    const float* __restrict__ b1, __nv_bfloat16* __restrict__ y1)
{
    extern __shared__ __nv_bfloat16 smb[];
    int d = blockIdx.x >> 6, h = blockIdx.x & 63;
    int tx = threadIdx.x;
    int warp = tx >> 5, lane = tx & 31;
    int gid = lane >> 2, tig = lane & 3;
    int wm = warp >> 1, wn = warp & 1;
    float acc[2][4] = {};

    auto load_phase = [&](int p, int buf) {
        int kd = p / 3, kh = p - kd * 3;
        int dd = d + kd - 1, hh = h + kh - 1;
        bool rowv = ((unsigned)dd < 8u) && ((unsigned)hh < 64u);
        __nv_bfloat16* in_s = smb + buf * C1_SE;
        __nv_bfloat16* w_s  = in_s + 66 * 104;
        const __nv_bfloat16* src_row = xn + ((size_t)(dd * HH + hh) * WW) * CCH;
        for (int idx = tx; idx < 792; idx += 256) {
            int r = idx / 12, c = idx - r * 12;
            int wv = r - 1;
            bool v = rowv && (unsigned)wv < 64u;
            const void* g = v ? (const void*)(src_row + wv * CCH + c * 8) : (const void*)xn;
            cpa16(in_s + r * 104 + c * 8, g, v);
        }
        const __nv_bfloat16* wsrc = w1r + (size_t)p * 3 * (CMP * CCH);
        for (int idx = tx; idx < 1152; idx += 256) {
            int r = idx / 12, c = idx - r * 12;
            cpa16(w_s + r * 104 + c * 8, wsrc + idx * 8, true);
        }
        cpa_commit();
    };

    load_phase(0, 0);
    for (int p = 0; p < 9; p++) {
        cpa_wait<0>();
        __syncthreads();
        if (p < 8) load_phase(p + 1, (p + 1) & 1);
        __nv_bfloat16* in_s = smb + (p & 1) * C1_SE;
        __nv_bfloat16* w_s  = in_s + 66 * 104;
        unsigned in_u = (unsigned)__cvta_generic_to_shared(in_s);
        #pragma unroll
        for (int kw = 0; kw < 3; kw++) {
            #pragma unroll
            for (int ks = 0; ks < 6; ks++) {
                unsigned af[4];
                ldsm4(af, in_u + 2u * ((wm * 16 + kw + (lane & 15)) * 104
                                       + ks * 16 + ((lane >> 4) << 3)));
                unsigned bf[4];
                ldsmB(bf, w_s + (kw * 32 + wn * 16) * 104 + ks * 16, 104, lane);
                mma16(acc[0], af, bf);
                mma16(acc[1], af, bf + 2);
            }
        }
    }
    __nv_bfloat16* orow = y1 + (size_t)(d * HH + h) * WW * CMP;
    #pragma unroll
    for (int nt = 0; nt < 2; nt++) {
        int oc = wn * 16 + nt * 8 + tig * 2;
        float bb0 = b1[oc], bb1 = b1[oc + 1];
        #pragma unroll
        for (int half = 0; half < 2; half++) {
            int v = wm * 16 + gid + half * 8;
            *(unsigned*)(orow + v * CMP + oc) =
                pack2(gelu_exact(acc[nt][half * 2 + 0] + bb0),
                      gelu_exact(acc[nt][half * 2 + 1] + bb1));
        }
    }
}

// ---------------- conv2: 32->96, 2-stage cp.async + fused pool partials ----------------
#define C2_SE (354 * 40)
__global__ __launch_bounds__(256) void conv2_kernel(
    const __nv_bfloat16* __restrict__ y1, const __nv_bfloat16* __restrict__ w2r,
    const float* __restrict__ b2, __nv_bfloat16* __restrict__ y2, float* __restrict__ part)
{
    extern __shared__ __nv_bfloat16 smb[];
    int d = blockIdx.x >> 6, h = blockIdx.x & 63;
    int tx = threadIdx.x;
    int warp = tx >> 5, lane = tx & 31;
    int gid = lane >> 2, tig = lane & 3;
    int wm = warp >> 1, wn = warp & 1;
    float acc[6][4] = {};

    auto load_phase = [&](int p, int buf) {
        int kd = p / 3, kh = p - kd * 3;
        int dd = d + kd - 1, hh = h + kh - 1;
        bool rowv = ((unsigned)dd < 8u) && ((unsigned)hh < 64u);
        __nv_bfloat16* in_s = smb + buf * C2_SE;
        __nv_bfloat16* w_s  = in_s + 66 * 40;
        const __nv_bfloat16* src_row = y1 + ((size_t)(dd * HH + hh) * WW) * CMP;
        for (int idx = tx; idx < 264; idx += 256) {
            int r = idx >> 2, c = idx & 3;
            int wv = r - 1;
            bool v = rowv && (unsigned)wv < 64u;
            const void* g = v ? (const void*)(src_row + wv * CMP + c * 8) : (const void*)y1;
            cpa16(in_s + r * 40 + c * 8, g, v);
        }
        const __nv_bfloat16* wsrc = w2r + (size_t)p * 3 * (CCH * CMP);
        for (int idx = tx; idx < 1152; idx += 256) {
            int r = idx >> 2, c = idx & 3;
            cpa16(w_s + r * 40 + c * 8, wsrc + idx * 8, true);
        }
        cpa_commit();
    };

    load_phase(0, 0);
    for (int p = 0; p < 9; p++) {
        cpa_wait<0>();
        __syncthreads();
        if (p < 8) load_phase(p + 1, (p + 1) & 1);
        __nv_bfloat16* in_s = smb + (p & 1) * C2_SE;
        __nv_bfloat16* w_s  = in_s + 66 * 40;
        unsigned in_u = (unsigned)__cvta_generic_to_shared(in_s);
        #pragma unroll
        for (int kw = 0; kw < 3; kw++) {
            #pragma unroll
            for (int ks = 0; ks < 2; ks++) {
                unsigned af[4];
                ldsm4(af, in_u + 2u * ((wm * 16 + kw + (lane & 15)) * 40
                                       + ks * 16 + ((lane >> 4) << 3)));
                #pragma unroll
                for (int np = 0; np < 3; np++) {
                    unsigned bf[4];
                    ldsmB(bf, w_s + (kw * 96 + wn * 48 + np * 16) * 40 + ks * 16, 40, lane);
                    mma16(acc[np * 2], af, bf);
                    mma16(acc[np * 2 + 1], af, bf + 2);
                }
            }
        }
    }
    __nv_bfloat16* orow = y2 + (size_t)(d * HH + h) * WW * CCH;
    float ch0[6], ch1[6];
    #pragma unroll
    for (int nt = 0; nt < 6; nt++) {
        int oc = wn * 48 + nt * 8 + tig * 2;
        float bb0 = b2[oc], bb1 = b2[oc + 1];
        #pragma unroll
        for (int half = 0; half < 2; half++) {
            int v = wm * 16 + gid + half * 8;
            *(unsigned*)(orow + v * CCH + oc) =
                pack2(acc[nt][half * 2 + 0] + bb0, acc[nt][half * 2 + 1] + bb1);
        }
        ch0[nt] = acc[nt][0] + acc[nt][2] + 2.0f * bb0;
        ch1[nt] = acc[nt][1] + acc[nt][3] + 2.0f * bb1;
    }
    #pragma unroll
    for (int nt = 0; nt < 6; nt++) {
        #pragma unroll
        for (int m = 4; m < 32; m <<= 1) {
            ch0[nt] += __shfl_xor_sync(0xffffffffu, ch0[nt], m);
            ch1[nt] += __shfl_xor_sync(0xffffffffu, ch1[nt], m);
        }
    }
    __syncthreads();
    float* ws = (float*)smb;
    if (gid == 0) {
        #pragma unroll
        for (int nt = 0; nt < 6; nt++) {
            int oc = wn * 48 + nt * 8 + tig * 2;
            ws[warp * 96 + oc] = ch0[nt];
            ws[warp * 96 + oc + 1] = ch1[nt];
        }
    }
    __syncthreads();
    if (tx < 96) {
        int wn2 = tx / 48;
        float s = ws[wn2 * 96 + tx] + ws[(wn2 + 2) * 96 + tx]
                + ws[(wn2 + 4) * 96 + tx] + ws[(wn2 + 6) * 96 + tx];
        part[blockIdx.x * 96 + tx] = s;
    }
}

// ---------------- channel attention ----------------
__global__ void ca_kernel(const float* __restrict__ part,
                          const float* __restrict__ ca1w, const float* __restrict__ ca1b,
                          const float* __restrict__ ca2w, const float* __restrict__ ca2b,
                          float* __restrict__ att)
{
    __shared__ float p[CCH], hs[3];
    int tx = threadIdx.x;
    float s = 0.f;
    for (int b = 0; b < 512; b++) s += part[b * CCH + tx];
    p[tx] = s * (1.0f / (float)LTOK);
    __syncthreads();
    if (tx < 3) {
        float a = ca1b[tx];
        for (int c = 0; c < CCH; c++) a += ca1w[tx * CCH + c] * p[c];
        hs[tx] = fmaxf(a, 0.f);
    }
    __syncthreads();
    float a = ca2b[tx];
    #pragma unroll
    for (int k = 0; k < 3; k++) a += ca2w[tx * 3 + k] * hs[k];
    att[tx] = 1.0f / (1.0f + expf(-a));
}

// ---------------- qkv GEMM (128-row tile, K=96, bf16 out) ----------------
__global__ __launch_bounds__(256) void gemm_qkv(
    const __nv_bfloat16* __restrict__ A, const __nv_bfloat16* __restrict__ Wt,
    const float* __restrict__ bias, __nv_bfloat16* __restrict__ Cout, int Nn)
{
    extern __shared__ __nv_bfloat16 smb[];
    int m0 = blockIdx.x * 128, n0 = blockIdx.y * 96;
    int tx = threadIdx.x;
    int warp = tx >> 5, lane = tx & 31;
    int wm = warp >> 1, wn = warp & 1;
    int gid = lane >> 2, tig = lane & 3;
    float acc[2][6][4] = {};
    for (int idx = tx; idx < 1536; idx += 256) {
        int r = idx / 12, c = idx - r * 12;
        *(uint4*)(smb + r * 104 + c * 8) = *(const uint4*)(A + (size_t)(m0 + r) * 96 + c * 8);
    }
    for (int idx = tx; idx < 1152; idx += 256) {
        int r = idx / 12, c = idx - r * 12;
        *(uint4*)(smb + (128 + r) * 104 + c * 8) = *(const uint4*)(Wt + (size_t)(n0 + r) * 96 + c * 8);
    }
    __syncthreads();
    __nv_bfloat16* w_s = smb + 128 * 104;
    unsigned a_u = (unsigned)__cvta_generic_to_shared(smb);
    #pragma unroll
    for (int ks = 0; ks < 6; ks++) {
        unsigned af[2][4];
        #pragma unroll
        for (int mt = 0; mt < 2; mt++)
            ldsm4(af[mt], a_u + 2u * ((wm * 32 + mt * 16 + (lane & 15)) * 104
                                      + ks * 16 + ((lane >> 4) << 3)));
        #pragma unroll
        for (int np = 0; np < 3; np++) {
            unsigned bf[4];
            ldsmB(bf, w_s + (wn * 48 + np * 16) * 104 + ks * 16, 104, lane);
            #pragma unroll
            for (int mt = 0; mt < 2; mt++) {
                mma16(acc[mt][np * 2], af[mt], bf);
                mma16(acc[mt][np * 2 + 1], af[mt], bf + 2);
            }
        }
    }
    #pragma unroll
    for (int mt = 0; mt < 2; mt++) {
        #pragma unroll
        for (int nt = 0; nt < 6; nt++) {
            int cc = n0 + wn * 48 + nt * 8 + tig * 2;
            float bb0 = bias[cc], bb1 = bias[cc + 1];
            #pragma unroll
            for (int half = 0; half < 2; half++) {
                int r = m0 + wm * 32 + mt * 16 + gid + half * 8;
                size_t idx = (size_t)r * Nn + cc;
                *(unsigned*)(Cout + idx) = pack2(acc[mt][nt][half * 2 + 0] + bb0,
                                                 acc[mt][nt][half * 2 + 1] + bb1);
            }
        }
    }
}

// ---------------- fused MLP: out = x1 + gelu(xn2@f1w+b1)@f2w + b2 ----------------
#define MLP_A  0
#define MLP_W  (64 * 104)
#define MLP_H  (MLP_W + 2 * 96 * 104)
#define MLP_SE (MLP_H + 4 * 64 * 104)
__global__ __launch_bounds__(256) void mlp_kernel(
    const __nv_bfloat16* __restrict__ xn2, const __nv_bfloat16* __restrict__ f1w,
    const float* __restrict__ fb1, const __nv_bfloat16* __restrict__ f2w,
    const float* __restrict__ fb2, const float* __restrict__ x1,
    float* __restrict__ out)
{
    extern __shared__ __nv_bfloat16 smb[];
    __nv_bfloat16* a_s = smb + MLP_A;
    __nv_bfloat16* h_s = smb + MLP_H;
    int m0 = blockIdx.x * 64;
    int tx = threadIdx.x;
    int warp = tx >> 5, lane = tx & 31;
    int wm = warp >> 1, wn = warp & 1;
    int gid = lane >> 2, tig = lane & 3;

    for (int idx = tx; idx < 768; idx += 256) {
        int r = idx / 12, c = idx - r * 12;
        *(uint4*)(a_s + r * 104 + c * 8) = *(const uint4*)(xn2 + (size_t)(m0 + r) * 96 + c * 8);
    }
    auto load_w = [&](int ph, int buf) {
        __nv_bfloat16* w_s = smb + MLP_W + buf * (96 * 104);
        const __nv_bfloat16* src = (ph < 4)
            ? f1w + (size_t)(ph * 96) * 96
            : f2w + (size_t)(ph - 4) * 96;
        size_t rstride = (ph < 4) ? 96 : 384;
        for (int idx = tx; idx < 1152; idx += 256) {
            int r = idx / 12, c = idx - r * 12;
            cpa16(w_s + r * 104 + c * 8, src + (size_t)r * rstride + c * 8, true);
        }
        cpa_commit();
    };
    load_w(0, 0);

    float acc[6][4] = {};
    unsigned a_u = (unsigned)__cvta_generic_to_shared(a_s);
    unsigned h_u = (unsigned)__cvta_generic_to_shared(h_s);

    for (int ph = 0; ph < 8; ph++) {
        cpa_wait<0>();
        __syncthreads();
        if (ph < 7) load_w(ph + 1, (ph + 1) & 1);
        __nv_bfloat16* w_s = smb + MLP_W + (ph & 1) * (96 * 104);
        if (ph < 4) {
            #pragma unroll
            for (int nt = 0; nt < 6; nt++)
                #pragma unroll
                for (int e = 0; e < 4; e++) acc[nt][e] = 0.f;
            #pragma unroll
            for (int ks = 0; ks < 6; ks++) {
                unsigned af[4];
                ldsm4(af, a_u + 2u * ((wm * 16 + (lane & 15)) * 104
                                      + ks * 16 + ((lane >> 4) << 3)));
                #pragma unroll
                for (int np = 0; np < 3; np++) {
                    unsigned bf[4];
                    ldsmB(bf, w_s + (wn * 48 + np * 16) * 104 + ks * 16, 104, lane);
                    mma16(acc[np * 2], af, bf);
                    mma16(acc[np * 2 + 1], af, bf + 2);
                }
            }
            __nv_bfloat16* hc = h_s + ph * (64 * 104);
            #pragma unroll
            for (int nt = 0; nt < 6; nt++) {
                int cc = wn * 48 + nt * 8 + tig * 2;
                float bb0 = fb1[ph * 96 + cc], bb1 = fb1[ph * 96 + cc + 1];
                #pragma unroll
                for (int half = 0; half < 2; half++) {
                    int rl = wm * 16 + gid + half * 8;
                    *(unsigned*)(hc + rl * 104 + cc) =
                        pack2(gelu_exact(acc[nt][half * 2 + 0] + bb0),
                              gelu_exact(acc[nt][half * 2 + 1] + bb1));
                }
            }
        } else {
            int kc = ph - 4;
            if (kc == 0) {
                #pragma unroll
                for (int nt = 0; nt < 6; nt++)
                    #pragma unroll
                    for (int e = 0; e < 4; e++) acc[nt][e] = 0.f;
            }
            unsigned hc_u = h_u + 2u * kc * (64 * 104);
            #pragma unroll
            for (int ks = 0; ks < 6; ks++) {
                unsigned af[4];
                ldsm4(af, hc_u + 2u * ((wm * 16 + (lane & 15)) * 104
                                       + ks * 16 + ((lane >> 4) << 3)));
                #pragma unroll
                for (int np = 0; np < 3; np++) {
                    unsigned bf[4];
                    ldsmB(bf, w_s + (wn * 48 + np * 16) * 104 + ks * 16, 104, lane);
                    mma16(acc[np * 2], af, bf);
                    mma16(acc[np * 2 + 1], af, bf + 2);
                }
            }
        }
    }
    #pragma unroll
    for (int nt = 0; nt < 6; nt++) {
        int cc = wn * 48 + nt * 8 + tig * 2;
        float bb0 = fb2[cc], bb1 = fb2[cc + 1];
        #pragma unroll
        for (int half = 0; half < 2; half++) {
            int r = m0 + wm * 16 + gid + half * 8;
            size_t idx = (size_t)r * 96 + cc;
            float2 r1 = *(const float2*)(x1 + idx);
            float2 o2;
            o2.x = r1.x + acc[nt][half * 2 + 0] + bb0;
            o2.y = r1.y + acc[nt][half * 2 + 1] + bb1;
            *(float2*)(out + idx) = o2;
        }
    }
}

// ---------------- proj GEMM + residual merge + fused LayerNorm2 ----------------
__global__ __launch_bounds__(256) void gemm_proj_ln(
    const __nv_bfloat16* __restrict__ A, const __nv_bfloat16* __restrict__ Wt,
    const float* __restrict__ bias,
    const float* __restrict__ res1, const __nv_bfloat16* __restrict__ res2,
    const float* __restrict__ att,
    const float* __restrict__ n2g, const float* __restrict__ n2b,
    float* __restrict__ x1, __nv_bfloat16* __restrict__ xn2)
{
    extern __shared__ __nv_bfloat16 smb[];
    __nv_bfloat16* a_s = smb;
    __nv_bfloat16* w_s = smb + 128 * 104;
    float* red_s = (float*)smb;
    float* red_q = red_s + 256;
    unsigned a_u = (unsigned)__cvta_generic_to_shared(a_s);
    int m0 = blockIdx.x * 128;
    int tx = threadIdx.x;
    int warp = tx >> 5, lane = tx & 31;
    int wm = warp >> 1, wn = warp & 1;
    int gid = lane >> 2, tig = lane & 3;
    float acc[2][6][4] = {};
    {
        for (int idx = tx; idx < 1536; idx += 256) {
            int r = idx / 12, c = idx - r * 12;
            *(uint4*)(a_s + r * 104 + c * 8) = *(const uint4*)(A + (size_t)(m0 + r) * 96 + c * 8);
        }
        for (int idx = tx; idx < 1152; idx += 256) {
            int r = idx / 12, c = idx - r * 12;
            *(uint4*)(w_s + r * 104 + c * 8) = *(const uint4*)(Wt + (size_t)r * 96 + c * 8);
        }
        __syncthreads();
        #pragma unroll
        for (int ks = 0; ks < 6; ks++) {
            unsigned af[2][4];
            #pragma unroll
            for (int mt = 0; mt < 2; mt++)
                ldsm4(af[mt], a_u + 2u * ((wm * 32 + mt * 16 + (lane & 15)) * 104
                                          + ks * 16 + ((lane >> 4) << 3)));
            #pragma unroll
            for (int np = 0; np < 3; np++) {
                unsigned bf[4];
                ldsmB(bf, w_s + (wn * 48 + np * 16) * 104 + ks * 16, 104, lane);
                #pragma unroll
                for (int mt = 0; mt < 2; mt++) {
                    mma16(acc[mt][np * 2], af[mt], bf);
                    mma16(acc[mt][np * 2 + 1], af[mt], bf + 2);
                }
            }
        }
    }
    __syncthreads();

    float rs[2][2] = {}, rq[2][2] = {};
    #pragma unroll
    for (int mt = 0; mt < 2; mt++) {
        #pragma unroll
        for (int nt = 0; nt < 6; nt++) {
            int cc = wn * 48 + nt * 8 + tig * 2;
            float bb0 = bias[cc], bb1 = bias[cc + 1];
            float a0 = att[cc] * 0.01f, a1 = att[cc + 1] * 0.01f;
            #pragma unroll
            for (int half = 0; half < 2; half++) {
                int r = m0 + wm * 32 + mt * 16 + gid + half * 8;
                size_t idx = (size_t)r * 96 + cc;
                float2 r1 = *(const float2*)(res1 + idx);
                float2 r2 = __bfloat1622float2(*(const __nv_bfloat162*)(res2 + idx));
                float v0 = r1.x + acc[mt][nt][half * 2 + 0] + bb0 + r2.x * a0;
                float v1 = r1.y + acc[mt][nt][half * 2 + 1] + bb1 + r2.y * a1;
                acc[mt][nt][half * 2 + 0] = v0;
                acc[mt][nt][half * 2 + 1] = v1;
                *(float2*)(x1 + idx) = make_float2(v0, v1);
                rs[mt][half] += v0 + v1;
                rq[mt][half] += v0 * v0 + v1 * v1;
            }
        }
    }
    #pragma unroll
    for (int mt = 0; mt < 2; mt++)
        #pragma unroll
        for (int half = 0; half < 2; half++) {
            float s = rs[mt][half], q = rq[mt][half];
            s += __shfl_xor_sync(0xffffffffu, s, 1);
            s += __shfl_xor_sync(0xffffffffu, s, 2);
            q += __shfl_xor_sync(0xffffffffu, q, 1);
            q += __shfl_xor_sync(0xffffffffu, q, 2);
            if (tig == 0) {
                int lr = wm * 32 + mt * 16 + half * 8 + gid;
                red_s[lr * 2 + wn] = s;
                red_q[lr * 2 + wn] = q;
            }
        }
    __syncthreads();
    #pragma unroll
    for (int mt = 0; mt < 2; mt++) {
        #pragma unroll
        for (int half = 0; half < 2; half++) {
            int lr = wm * 32 + mt * 16 + half * 8 + gid;
            float sum = red_s[lr * 2] + red_s[lr * 2 + 1];
            float sq  = red_q[lr * 2] + red_q[lr * 2 + 1];
            float mean = sum * (1.0f / 96.0f);
            float var = sq * (1.0f / 96.0f) - mean * mean;
            float inv = rsqrtf(var + 1e-5f);
            int r = m0 + lr;
            #pragma unroll
            for (int nt = 0; nt < 6; nt++) {
                int cc = wn * 48 + nt * 8 + tig * 2;
                float g0 = n2g[cc], g1 = n2g[cc + 1];
                float b0 = n2b[cc], b1 = n2b[cc + 1];
                float v0 = (acc[mt][nt][half * 2 + 0] - mean) * inv * g0 + b0;
                float v1 = (acc[mt][nt][half * 2 + 1] - mean) * inv * g1 + b1;
                *(unsigned*)(xn2 + (size_t)r * 96 + cc) = pack2(v0, v1);
            }
        }
    }
}

// ---------------- attention ----------------
#define OFF_Q  0
#define OFF_K  3072
#define OFF_V  27648
#define OFF_R1 44288
#define OFF_R2 45312
#define OFF_OR 46336
#define SMEM_ATTN 62720

__device__ __forceinline__ int wtok(int j, int base) {
    return ((j >> 6) << 12) + base + (((j >> 3) & 7) << 6) + (j & 7);
}

__global__ __launch_bounds__(512) void attn_kernel(
    const __nv_bfloat16* __restrict__ qkv, const __nv_bfloat16* __restrict__ biasb,
    __nv_bfloat16* __restrict__ o)
{
    extern __shared__ char smc[];
    __nv_bfloat16* q_s = (__nv_bfloat16*)(smc + OFF_Q);
    __nv_bfloat16* k_s = (__nv_bfloat16*)(smc + OFF_K);
    __nv_bfloat16* v_t = (__nv_bfloat16*)(smc + OFF_V);
    float* red1 = (float*)(smc + OFF_R1);
    float* red2 = (float*)(smc + OFF_R2);
    float* o_red = (float*)(smc + OFF_OR);
    unsigned q_u = (unsigned)__cvta_generic_to_shared(q_s);

    int blk = blockIdx.x;
    int qc = blk & 7;
    int head = (blk >> 3) % 6;
    int win = blk / 48;
    int base = (win >> 3) * 512 + (win & 7) * 8;
    int m0 = qc * 64;
    int tx = threadIdx.x;
    int warp = tx >> 5, lane = tx & 31;
    int gid = lane >> 2, tig = lane & 3;
    int wm = warp >> 2, wn = warp & 3;
    int r0 = wm * 16, j0 = wn * 128;

    for (int idx = tx; idx < 1024; idx += 512) {
        int j = idx >> 1, half = idx & 1;
        int t = wtok(j, base);
        const __nv_bfloat16* p = qkv + (size_t)t * 288 + head * 16 + half * 8;
        *(uint4*)(k_s + j * 24 + half * 8) = *(const uint4*)(p + 96);
        uint4 v4 = *(const uint4*)(p + 192);
        const __nv_bfloat16* vp = (const __nv_bfloat16*)&v4;
        #pragma unroll
        for (int dd2 = 0; dd2 < 8; dd2++)
            v_t[(half * 8 + dd2) * 520 + j] = vp[dd2];
    }
    if (tx < 128) {
        int i = tx >> 1, half = tx & 1;
        int t = wtok(m0 + i, base);
        uint4 raw = *(const uint4*)(qkv + (size_t)t * 288 + head * 16 + half * 8);
        const __nv_bfloat16* rp = (const __nv_bfloat16*)&raw;
        unsigned pk[4];
        #pragma unroll
        for (int e = 0; e < 4; e++)
            pk[e] = pack2(__bfloat162float(rp[e * 2]) * 0.25f,
                          __bfloat162float(rp[e * 2 + 1]) * 0.25f);
        *(uint4*)(q_s + i * 24 + half * 8) = *(uint4*)pk;
    }
    __syncthreads();

    float acc[16][4] = {};
    {
        unsigned aq[4];
        ldsm4(aq, q_u + 2u * ((r0 + (lane & 15)) * 24 + ((lane >> 4) << 3)));
        #pragma unroll
        for (int np = 0; np < 8; np++) {
            unsigned bf[4];
            ldsmB(bf, k_s + (j0 + np * 16) * 24, 24, lane);
            mma16(acc[np * 2], aq, bf);
            mma16(acc[np * 2 + 1], aq, bf + 2);
        }
        const __nv_bfloat16* bbA = biasb + ((size_t)head * 512 + (m0 + r0 + gid)) * 512 + j0 + tig * 2;
        const __nv_bfloat16* bbB = bbA + 8 * 512;
        #pragma unroll
        for (int nt = 0; nt < 16; nt++) {
            float2 fa = __bfloat1622float2(*(const __nv_bfloat162*)(bbA + nt * 8));
            float2 fb = __bfloat1622float2(*(const __nv_bfloat162*)(bbB + nt * 8));
            acc[nt][0] += fa.x; acc[nt][1] += fa.y;
            acc[nt][2] += fb.x; acc[nt][3] += fb.y;
        }
    }
    {
        float mA = -1e30f, mB = -1e30f;
        #pragma unroll
        for (int nt = 0; nt < 16; nt++) {
            mA = fmaxf(mA, fmaxf(acc[nt][0], acc[nt][1]));
            mB = fmaxf(mB, fmaxf(acc[nt][2], acc[nt][3]));
        }
        mA = fmaxf(mA, __shfl_xor_sync(0xffffffffu, mA, 1));
        mA = fmaxf(mA, __shfl_xor_sync(0xffffffffu, mA, 2));
        mB = fmaxf(mB, __shfl_xor_sync(0xffffffffu, mB, 1));
        mB = fmaxf(mB, __shfl_xor_sync(0xffffffffu, mB, 2));
        if (tig == 0) {
            red1[(r0 + gid) * 4 + wn] = mA;
            red1[(r0 + gid + 8) * 4 + wn] = mB;
        }
        __syncthreads();
        mA = fmaxf(fmaxf(red1[(r0 + gid) * 4 + 0], red1[(r0 + gid) * 4 + 1]),
                   fmaxf(red1[(r0 + gid) * 4 + 2], red1[(r0 + gid) * 4 + 3]));
        mB = fmaxf(fmaxf(red1[(r0 + gid + 8) * 4 + 0], red1[(r0 + gid + 8) * 4 + 1]),
                   fmaxf(red1[(r0 + gid + 8) * 4 + 2], red1[(r0 + gid + 8) * 4 + 3]));
        float sA = 0.f, sB = 0.f;
        #pragma unroll
        for (int nt = 0; nt < 16; nt++) {
            acc[nt][0] = __expf(acc[nt][0] - mA);
            acc[nt][1] = __expf(acc[nt][1] - mA);
            acc[nt][2] = __expf(acc[nt][2] - mB);
            acc[nt][3] = __expf(acc[nt][3] - mB);
            sA += acc[nt][0] + acc[nt][1];
            sB += acc[nt][2] + acc[nt][3];
        }
        sA += __shfl_xor_sync(0xffffffffu, sA, 1);
        sA += __shfl_xor_sync(0xffffffffu, sA, 2);
        sB += __shfl_xor_sync(0xffffffffu, sB, 1);
        sB += __shfl_xor_sync(0xffffffffu, sB, 2);
        if (tig == 0) {
            red2[(r0 + gid) * 4 + wn] = sA;
            red2[(r0 + gid + 8) * 4 + wn] = sB;
        }
        __syncthreads();
        sA = red2[(r0 + gid) * 4 + 0] + red2[(r0 + gid) * 4 + 1]
           + red2[(r0 + gid) * 4 + 2] + red2[(r0 + gid) * 4 + 3];
        sB = red2[(r0 + gid + 8) * 4 + 0] + red2[(r0 + gid + 8) * 4 + 1]
           + red2[(r0 + gid + 8) * 4 + 2] + red2[(r0 + gid + 8) * 4 + 3];
        float iA = 1.0f / sA, iB = 1.0f / sB;
        #pragma unroll
        for (int nt = 0; nt < 16; nt++) {
            acc[nt][0] *= iA; acc[nt][1] *= iA;
            acc[nt][2] *= iB; acc[nt][3] *= iB;
        }
    }

    float oa[2][4] = {};
    #pragma unroll
    for (int kk = 0; kk < 8; kk++) {
        unsigned af[4];
        af[0] = pack2(acc[2 * kk][0],     acc[2 * kk][1]);
        af[1] = pack2(acc[2 * kk][2],     acc[2 * kk][3]);
        af[2] = pack2(acc[2 * kk + 1][0], acc[2 * kk + 1][1]);
        af[3] = pack2(acc[2 * kk + 1][2], acc[2 * kk + 1][3]);
        unsigned bf[4];
        ldsmB(bf, v_t + j0 + kk * 16, 520, lane);
        mma16(oa[0], af, bf);
        mma16(oa[1], af, bf + 2);
    }
    {
        float* orp = o_red + (size_t)wn * 1024;
        #pragma unroll
        for (int dt = 0; dt < 2; dt++) {
            int dc = dt * 8 + tig * 2;
            *(float2*)(orp + (r0 + gid) * 16 + dc)     = make_float2(oa[dt][0], oa[dt][1]);
            *(float2*)(orp + (r0 + gid + 8) * 16 + dc) = make_float2(oa[dt][2], oa[dt][3]);
        }
    }
    __syncthreads();
    {
        int row = tx >> 3, d2 = tx & 7;
        int dim = d2 * 2;
        float v0 = 0.f, v1 = 0.f;
        #pragma unroll
        for (int p = 0; p < 4; p++) {
            v0 += o_red[p * 1024 + row * 16 + dim];
            v1 += o_red[p * 1024 + row * 16 + dim + 1];
        }
        int t = wtok(m0 + row, base);
        *(unsigned*)(o + (size_t)t * CCH + head * 16 + dim) = pack2(v0, v1);
    }
}

// ---------------- launch (round-13 champion schedule) ----------------
extern "C" void kernel_launch(void* const* d_in, const int* in_sizes, int n_in,
                              void* d_out, int out_size)
{
    (void)in_sizes; (void)n_in; (void)out_size;
    const float* x       = (const float*)d_in[0];
    const float* n1g     = (const float*)d_in[1];
    const float* n1b     = (const float*)d_in[2];
    const float* qkv_w   = (const float*)d_in[3];
    const float* qkv_b   = (const float*)d_in[4];
    const float* rpbt    = (const float*)d_in[5];
    const float* proj_w  = (const float*)d_in[6];
    const float* proj_b  = (const float*)d_in[7];
    const float* conv1_w = (const float*)d_in[8];
    const float* conv1_b = (const float*)d_in[9];
    const float* conv2_w = (const float*)d_in[10];
    const float* conv2_b = (const float*)d_in[11];
    const float* ca1_w   = (const float*)d_in[12];
    const float* ca1_b   = (const float*)d_in[13];
    const float* ca2_w   = (const float*)d_in[14];
    const float* ca2_b   = (const float*)d_in[15];
    const float* n2g     = (const float*)d_in[16];
    const float* n2b     = (const float*)d_in[17];
    const float* fc1_w   = (const float*)d_in[18];
    const float* fc1_b   = (const float*)d_in[19];
    const float* fc2_w   = (const float*)d_in[20];
    const float* fc2_b   = (const float*)d_in[21];
    const int*   rpi     = (const int*)d_in[22];
    float* out = (float*)d_out;

    __nv_bfloat16 *xn, *y1, *y2, *qkvb, *biasb, *ob, *xn2, *w1r, *w2r, *qw, *pw, *f1w, *f2w;
    float *part, *att, *x1;
    cudaGetSymbolAddress((void**)&xn,    g_xn);
    cudaGetSymbolAddress((void**)&y1,    g_y1);
    cudaGetSymbolAddress((void**)&y2,    g_y2);
    cudaGetSymbolAddress((void**)&part,  g_part);
    cudaGetSymbolAddress((void**)&att,   g_att);
    cudaGetSymbolAddress((void**)&qkvb,  g_qkv);
    cudaGetSymbolAddress((void**)&biasb, g_bias);
    cudaGetSymbolAddress((void**)&ob,    g_o);
    cudaGetSymbolAddress((void**)&x1,    g_x1);
    cudaGetSymbolAddress((void**)&xn2,   g_xn2);
    cudaGetSymbolAddress((void**)&w1r,   g_w1r);
    cudaGetSymbolAddress((void**)&w2r,   g_w2r);
    cudaGetSymbolAddress((void**)&qw,    g_qw);
    cudaGetSymbolAddress((void**)&pw,    g_pw);
    cudaGetSymbolAddress((void**)&f1w,   g_f1w);
    cudaGetSymbolAddress((void**)&f2w,   g_f2w);

    const int SMEM_CONV1 = 2 * C1_SE * 2;
    const int SMEM_CONV2 = 2 * C2_SE * 2;
    const int SMEM_G128  = (128 + 96) * 104 * 2;
    const int SMEM_MLP   = MLP_SE * 2;

    static bool s_init = false;
    static cudaStream_t sW, sC;
    static cudaEvent_t eFork, eLn, eW, eConv;
    if (!s_init) {
        cudaStreamCreateWithFlags(&sW, cudaStreamNonBlocking);
        cudaStreamCreateWithFlags(&sC, cudaStreamNonBlocking);
        cudaEventCreateWithFlags(&eFork, cudaEventDisableTiming);
        cudaEventCreateWithFlags(&eLn,   cudaEventDisableTiming);
        cudaEventCreateWithFlags(&eW,    cudaEventDisableTiming);
        cudaEventCreateWithFlags(&eConv, cudaEventDisableTiming);
        cudaFuncSetAttribute(conv1_kernel, cudaFuncAttributeMaxDynamicSharedMemorySize, SMEM_CONV1);
        cudaFuncSetAttribute(conv2_kernel, cudaFuncAttributeMaxDynamicSharedMemorySize, SMEM_CONV2);
        cudaFuncSetAttribute(gemm_qkv, cudaFuncAttributeMaxDynamicSharedMemorySize, SMEM_G128);
        cudaFuncSetAttribute(gemm_proj_ln, cudaFuncAttributeMaxDynamicSharedMemorySize, SMEM_G128);
        cudaFuncSetAttribute(mlp_kernel, cudaFuncAttributeMaxDynamicSharedMemorySize, SMEM_MLP);
        cudaFuncSetAttribute(attn_kernel, cudaFuncAttributeMaxDynamicSharedMemorySize, SMEM_ATTN);
        s_init = true;
    }

    cudaEventRecord(eFork, 0);

    cudaStreamWaitEvent(sW, eFork, 0);
    setup_w_kernel<<<1080, 256, 0, sW>>>(qkv_w, proj_w, fc1_w, fc2_w, conv1_w, conv2_w,
                                         qw, pw, f1w, f2w, w1r, w2r);
    cudaEventRecord(eW, sW);

    ln_kernel<<<LTOK / 8, 256>>>(x, n1g, n1b, xn);
    cudaEventRecord(eLn, 0);

    cudaStreamWaitEvent(sC, eLn, 0);
    cudaStreamWaitEvent(sC, eW, 0);
    conv1_kernel<<<512, 256, SMEM_CONV1, sC>>>(xn, w1r, conv1_b, y1);
    conv2_kernel<<<512, 256, SMEM_CONV2, sC>>>(y1, w2r, conv2_b, y2, part);
    ca_kernel<<<1, CCH, 0, sC>>>(part, ca1_w, ca1_b, ca2_w, ca2_b, att);
    cudaEventRecord(eConv, sC);

    setup_bias_kernel<<<3072, 256>>>(rpi, rpbt, biasb);
    cudaStreamWaitEvent(0, eW, 0);
    gemm_qkv<<<dim3(LTOK / 128, 3), 256, SMEM_G128>>>(xn, qw, qkv_b, qkvb, 288);
    attn_kernel<<<NWIN * HEADS * 8, 512, SMEM_ATTN>>>(qkvb, biasb, ob);

    cudaStreamWaitEvent(0, eConv, 0);
    gemm_proj_ln<<<LTOK / 128, 256, SMEM_G128>>>(
        ob, pw, proj_b, x, y2, att, n2g, n2b, x1, xn2);
    mlp_kernel<<<LTOK / 64, 256, SMEM_MLP>>>(xn2, f1w, fc1_b, f2w, fc2_b, x1, out);
}

// round 17
// speedup vs baseline: 1.1678x; 1.0961x over previous
#include <cuda_runtime.h>
#include <cuda_bf16.h>
#include <math.h>
#include <stdint.h>

#define DD 8
#define HH 64
#define WW 64
#define LTOK 32768
#define CCH 96
#define CMP 32
#define HID 384
#define HEADS 6
#define HDIM 16
#define NWIN 64
#define NTOK 512

// ---------------- scratch ----------------
__device__ __nv_bfloat16 g_xn  [LTOK * CCH];
__device__ __nv_bfloat16 g_y1  [LTOK * CMP];
__device__ __nv_bfloat16 g_y2  [LTOK * CCH];
__device__ float         g_part[512 * CCH];
__device__ float         g_att [CCH];
__device__ __nv_bfloat16 g_qkv [LTOK * 3 * CCH];
__device__ __nv_bfloat16 g_bias[HEADS * NTOK * NTOK];
__device__ __nv_bfloat16 g_o   [LTOK * CCH];
__device__ float         g_x1  [LTOK * CCH];
__device__ __nv_bfloat16 g_xn2 [LTOK * CCH];
__device__ __nv_bfloat16 g_w1r [27 * CMP * CCH];
__device__ __nv_bfloat16 g_w2r [27 * CCH * CMP];
__device__ __nv_bfloat16 g_qw  [288 * 96];
__device__ __nv_bfloat16 g_pw  [96 * 96];
__device__ __nv_bfloat16 g_f1w [384 * 96];
__device__ __nv_bfloat16 g_f2w [96 * 384];

__device__ __forceinline__ float gelu_exact(float v) {
    return 0.5f * v * (1.0f + erff(v * 0.70710678118654752f));
}
__device__ __forceinline__ unsigned pack2(float a, float b) {
    __nv_bfloat162 t = __floats2bfloat162_rn(a, b);
    return *reinterpret_cast<unsigned*>(&t);
}
__device__ __forceinline__ void ldsm4(unsigned* r, unsigned addr) {
    asm volatile("ldmatrix.sync.aligned.m8n8.x4.shared.b16 {%0,%1,%2,%3},[%4];"
                 : "=r"(r[0]), "=r"(r[1]), "=r"(r[2]), "=r"(r[3]) : "r"(addr));
}
__device__ __forceinline__ void ldsmB(unsigned* r, const __nv_bfloat16* base, int S, int lane) {
    int tq = lane & 7, sel = lane >> 3;
    const __nv_bfloat16* p = base + ((sel & 2) * 4 + tq) * S + (sel & 1) * 8;
    ldsm4(r, (unsigned)__cvta_generic_to_shared(p));
}
__device__ __forceinline__ void mma16(float* d, const unsigned* a, const unsigned* b) {
    asm volatile(
        "mma.sync.aligned.m16n8k16.row.col.f32.bf16.bf16.f32 "
        "{%0,%1,%2,%3},{%4,%5,%6,%7},{%8,%9},{%0,%1,%2,%3};"
        : "+f"(d[0]), "+f"(d[1]), "+f"(d[2]), "+f"(d[3])
        : "r"(a[0]), "r"(a[1]), "r"(a[2]), "r"(a[3]), "r"(b[0]), "r"(b[1]));
}
__device__ __forceinline__ void cpa16(__nv_bfloat16* s, const void* g, bool v) {
    unsigned sa = (unsigned)__cvta_generic_to_shared(s);
    int sz = v ? 16 : 0;
    asm volatile("cp.async.cg.shared.global [%0], [%1], 16, %2;" :: "r"(sa), "l"(g), "r"(sz));
}
__device__ __forceinline__ void cpa_commit() { asm volatile("cp.async.commit_group;"); }
template <int N> __device__ __forceinline__ void cpa_wait() {
    asm volatile("cp.async.wait_group %0;" :: "n"(N));
}

// ---------------- LayerNorm ----------------
__global__ void ln_kernel(const float* __restrict__ x, const float* __restrict__ g,
                          const float* __restrict__ b, __nv_bfloat16* __restrict__ out)
{
    int row  = blockIdx.x * 8 + (threadIdx.x >> 5);
    int lane = threadIdx.x & 31;
    const float* xr = x + (size_t)row * CCH;
    float v0 = xr[lane], v1 = xr[lane + 32], v2 = xr[lane + 64];
    float s = v0 + v1 + v2;
    #pragma unroll
    for (int o = 16; o; o >>= 1) s += __shfl_xor_sync(0xffffffffu, s, o);
    float mu = s * (1.0f / 96.0f);
    float d0 = v0 - mu, d1 = v1 - mu, d2 = v2 - mu;
    float q = d0 * d0 + d1 * d1 + d2 * d2;
    #pragma unroll
    for (int o = 16; o; o >>= 1) q += __shfl_xor_sync(0xffffffffu, q, o);
    float inv = rsqrtf(q * (1.0f / 96.0f) + 1e-5f);
    __nv_bfloat16* orow = out + (size_t)row * CCH;
    orow[lane]      = __float2bfloat16(d0 * inv * g[lane]      + b[lane]);
    orow[lane + 32] = __float2bfloat16(d1 * inv * g[lane + 32] + b[lane + 32]);
    orow[lane + 64] = __float2bfloat16(d2 * inv * g[lane + 64] + b[lane + 64]);
}

// ---------------- setup: weights only (1080 blocks) ----------------
__global__ void setup_w_kernel(
    const float* __restrict__ qkv_w, const float* __restrict__ proj_w,
    const float* __restrict__ fc1_w, const float* __restrict__ fc2_w,
    const float* __restrict__ conv1_w, const float* __restrict__ conv2_w,
    __nv_bfloat16* __restrict__ qw, __nv_bfloat16* __restrict__ pw,
    __nv_bfloat16* __restrict__ f1w, __nv_bfloat16* __restrict__ f2w,
    __nv_bfloat16* __restrict__ w1r, __nv_bfloat16* __restrict__ w2r)
{
    int b = blockIdx.x, tx = threadIdx.x;
    if (b < 108) {
        int i = b * 256 + tx;
        if (i < 288 * 96) qw[i] = __float2bfloat16(qkv_w[i]);
    } else if (b < 144) {
        int i = (b - 108) * 256 + tx;
        if (i < 96 * 96) pw[i] = __float2bfloat16(proj_w[i]);
    } else if (b < 288) {
        int i = (b - 144) * 256 + tx;
        if (i < 384 * 96) f1w[i] = __float2bfloat16(fc1_w[i]);
    } else if (b < 432) {
        int i = (b - 288) * 256 + tx;
        if (i < 96 * 384) f2w[i] = __float2bfloat16(fc2_w[i]);
    } else if (b < 756) {
        int tid = (b - 432) * 256 + tx;
        if (tid < CMP * CCH * 27) {
            int o = tid / (CCH * 27);
            int rem = tid - o * (CCH * 27);
            int c = rem / 27;
            int tap = rem - c * 27;
            w1r[(tap * CMP + o) * CCH + c] = __float2bfloat16(conv1_w[tid]);
        }
    } else {
        int tid = (b - 756) * 256 + tx;
        if (tid < CCH * CMP * 27) {
            int o = tid / (CMP * 27);
            int rem = tid - o * (CMP * 27);
            int i = rem / 27;
            int tap = rem - i * 27;
            w2r[(tap * CCH + o) * CMP + i] = __float2bfloat16(conv2_w[tid]);
        }
    }
}

// ---------------- setup: bias expansion ----------------
__global__ void setup_bias_kernel(const int* __restrict__ rpi, const float* __restrict__ rpbt,
                                  __nv_bfloat16* __restrict__ biasb)
{
    int tid = blockIdx.x * 256 + threadIdx.x;
    int e = tid * 2;
    int h = e >> 18;
    int r = e & 262143;
    int2 ri = *(const int2*)(rpi + r);
    *(unsigned*)(biasb + e) = pack2(rpbt[ri.x * HEADS + h], rpbt[ri.y * HEADS + h]);
}

// ---------------- conv1: 96->32 + GELU, 2-stage cp.async ----------------
#define C1_SE (162 * 104)
__global__ __launch_bounds__(256) void conv1_kernel(
    const __nv_bfloat16* __restrict__ xn, const __nv_bfloat16* __restrict__ w1r,
    const float* __restrict__ b1, __nv_bfloat16* __restrict__ y1)
{
    extern __shared__ __nv_bfloat16 smb[];
    int d = blockIdx.x >> 6, h = blockIdx.x & 63;
    int tx = threadIdx.x;
    int warp = tx >> 5, lane = tx & 31;
    int gid = lane >> 2, tig = lane & 3;
    int wm = warp >> 1, wn = warp & 1;
    float acc[2][4] = {};

    auto load_phase = [&](int p, int buf) {
        int kd = p / 3, kh = p - kd * 3;
        int dd = d + kd - 1, hh = h + kh - 1;
        bool rowv = ((unsigned)dd < 8u) && ((unsigned)hh < 64u);
        __nv_bfloat16* in_s = smb + buf * C1_SE;
        __nv_bfloat16* w_s  = in_s + 66 * 104;
        const __nv_bfloat16* src_row = xn + ((size_t)(dd * HH + hh) * WW) * CCH;
        for (int idx = tx; idx < 792; idx += 256) {
            int r = idx / 12, c = idx - r * 12;
            int wv = r - 1;
            bool v = rowv && (unsigned)wv < 64u;
            const void* g = v ? (const void*)(src_row + wv * CCH + c * 8) : (const void*)xn;
            cpa16(in_s + r * 104 + c * 8, g, v);
        }
        const __nv_bfloat16* wsrc = w1r + (size_t)p * 3 * (CMP * CCH);
        for (int idx = tx; idx < 1152; idx += 256) {
            int r = idx / 12, c = idx - r * 12;
            cpa16(w_s + r * 104 + c * 8, wsrc + idx * 8, true);
        }
        cpa_commit();
    };

    load_phase(0, 0);
    for (int p = 0; p < 9; p++) {
        cpa_wait<0>();
        __syncthreads();
        if (p < 8) load_phase(p + 1, (p + 1) & 1);
        __nv_bfloat16* in_s = smb + (p & 1) * C1_SE;
        __nv_bfloat16* w_s  = in_s + 66 * 104;
        unsigned in_u = (unsigned)__cvta_generic_to_shared(in_s);
        #pragma unroll
        for (int kw = 0; kw < 3; kw++) {
            #pragma unroll
            for (int ks = 0; ks < 6; ks++) {
                unsigned af[4];
                ldsm4(af, in_u + 2u * ((wm * 16 + kw + (lane & 15)) * 104
                                       + ks * 16 + ((lane >> 4) << 3)));
                unsigned bf[4];
                ldsmB(bf, w_s + (kw * 32 + wn * 16) * 104 + ks * 16, 104, lane);
                mma16(acc[0], af, bf);
                mma16(acc[1], af, bf + 2);
            }
        }
    }
    __nv_bfloat16* orow = y1 + (size_t)(d * HH + h) * WW * CMP;
    #pragma unroll
    for (int nt = 0; nt < 2; nt++) {
        int oc = wn * 16 + nt * 8 + tig * 2;
        float bb0 = b1[oc], bb1 = b1[oc + 1];
        #pragma unroll
        for (int half = 0; half < 2; half++) {
            int v = wm * 16 + gid + half * 8;
            *(unsigned*)(orow + v * CMP + oc) =
                pack2(gelu_exact(acc[nt][half * 2 + 0] + bb0),
                      gelu_exact(acc[nt][half * 2 + 1] + bb1));
        }
    }
}

// ---------------- conv2: 32->96, 2-stage cp.async + fused pool partials ----------------
#define C2_SE (354 * 40)
__global__ __launch_bounds__(256) void conv2_kernel(
    const __nv_bfloat16* __restrict__ y1, const __nv_bfloat16* __restrict__ w2r,
    const float* __restrict__ b2, __nv_bfloat16* __restrict__ y2, float* __restrict__ part)
{
    extern __shared__ __nv_bfloat16 smb[];
    int d = blockIdx.x >> 6, h = blockIdx.x & 63;
    int tx = threadIdx.x;
    int warp = tx >> 5, lane = tx & 31;
    int gid = lane >> 2, tig = lane & 3;
    int wm = warp >> 1, wn = warp & 1;
    float acc[6][4] = {};

    auto load_phase = [&](int p, int buf) {
        int kd = p / 3, kh = p - kd * 3;
        int dd = d + kd - 1, hh = h + kh - 1;
        bool rowv = ((unsigned)dd < 8u) && ((unsigned)hh < 64u);
        __nv_bfloat16* in_s = smb + buf * C2_SE;
        __nv_bfloat16* w_s  = in_s + 66 * 40;
        const __nv_bfloat16* src_row = y1 + ((size_t)(dd * HH + hh) * WW) * CMP;
        for (int idx = tx; idx < 264; idx += 256) {
            int r = idx >> 2, c = idx & 3;
            int wv = r - 1;
            bool v = rowv && (unsigned)wv < 64u;
            const void* g = v ? (const void*)(src_row + wv * CMP + c * 8) : (const void*)y1;
            cpa16(in_s + r * 40 + c * 8, g, v);
        }
        const __nv_bfloat16* wsrc = w2r + (size_t)p * 3 * (CCH * CMP);
        for (int idx = tx; idx < 1152; idx += 256) {
            int r = idx >> 2, c = idx & 3;
            cpa16(w_s + r * 40 + c * 8, wsrc + idx * 8, true);
        }
        cpa_commit();
    };

    load_phase(0, 0);
    for (int p = 0; p < 9; p++) {
        cpa_wait<0>();
        __syncthreads();
        if (p < 8) load_phase(p + 1, (p + 1) & 1);
        __nv_bfloat16* in_s = smb + (p & 1) * C2_SE;
        __nv_bfloat16* w_s  = in_s + 66 * 40;
        unsigned in_u = (unsigned)__cvta_generic_to_shared(in_s);
        #pragma unroll
        for (int kw = 0; kw < 3; kw++) {
            #pragma unroll
            for (int ks = 0; ks < 2; ks++) {
                unsigned af[4];
                ldsm4(af, in_u + 2u * ((wm * 16 + kw + (lane & 15)) * 40
                                       + ks * 16 + ((lane >> 4) << 3)));
                #pragma unroll
                for (int np = 0; np < 3; np++) {
                    unsigned bf[4];
                    ldsmB(bf, w_s + (kw * 96 + wn * 48 + np * 16) * 40 + ks * 16, 40, lane);
                    mma16(acc[np * 2], af, bf);
                    mma16(acc[np * 2 + 1], af, bf + 2);
                }
            }
        }
    }
    __nv_bfloat16* orow = y2 + (size_t)(d * HH + h) * WW * CCH;
    float ch0[6], ch1[6];
    #pragma unroll
    for (int nt = 0; nt < 6; nt++) {
        int oc = wn * 48 + nt * 8 + tig * 2;
        float bb0 = b2[oc], bb1 = b2[oc + 1];
        #pragma unroll
        for (int half = 0; half < 2; half++) {
            int v = wm * 16 + gid + half * 8;
            *(unsigned*)(orow + v * CCH + oc) =
                pack2(acc[nt][half * 2 + 0] + bb0, acc[nt][half * 2 + 1] + bb1);
        }
        ch0[nt] = acc[nt][0] + acc[nt][2] + 2.0f * bb0;
        ch1[nt] = acc[nt][1] + acc[nt][3] + 2.0f * bb1;
    }
    #pragma unroll
    for (int nt = 0; nt < 6; nt++) {
        #pragma unroll
        for (int m = 4; m < 32; m <<= 1) {
            ch0[nt] += __shfl_xor_sync(0xffffffffu, ch0[nt], m);
            ch1[nt] += __shfl_xor_sync(0xffffffffu, ch1[nt], m);
        }
    }
    __syncthreads();
    float* ws = (float*)smb;
    if (gid == 0) {
        #pragma unroll
        for (int nt = 0; nt < 6; nt++) {
            int oc = wn * 48 + nt * 8 + tig * 2;
            ws[warp * 96 + oc] = ch0[nt];
            ws[warp * 96 + oc + 1] = ch1[nt];
        }
    }
    __syncthreads();
    if (tx < 96) {
        int wn2 = tx / 48;
        float s = ws[wn2 * 96 + tx] + ws[(wn2 + 2) * 96 + tx]
                + ws[(wn2 + 4) * 96 + tx] + ws[(wn2 + 6) * 96 + tx];
        part[blockIdx.x * 96 + tx] = s;
    }
}

// ---------------- channel attention ----------------
__global__ void ca_kernel(const float* __restrict__ part,
                          const float* __restrict__ ca1w, const float* __restrict__ ca1b,
                          const float* __restrict__ ca2w, const float* __restrict__ ca2b,
                          float* __restrict__ att)
{
    __shared__ float p[CCH], hs[3];
    int tx = threadIdx.x;
    float s = 0.f;
    for (int b = 0; b < 512; b++) s += part[b * CCH + tx];
    p[tx] = s * (1.0f / (float)LTOK);
    __syncthreads();
    if (tx < 3) {
        float a = ca1b[tx];
        for (int c = 0; c < CCH; c++) a += ca1w[tx * CCH + c] * p[c];
        hs[tx] = fmaxf(a, 0.f);
    }
    __syncthreads();
    float a = ca2b[tx];
    #pragma unroll
    for (int k = 0; k < 3; k++) a += ca2w[tx * 3 + k] * hs[k];
    att[tx] = 1.0f / (1.0f + expf(-a));
}

// ---------------- qkv GEMM (128-row tile, K=96, bf16 out) ----------------
__global__ __launch_bounds__(256) void gemm_qkv(
    const __nv_bfloat16* __restrict__ A, const __nv_bfloat16* __restrict__ Wt,
    const float* __restrict__ bias, __nv_bfloat16* __restrict__ Cout, int Nn)
{
    extern __shared__ __nv_bfloat16 smb[];
    int m0 = blockIdx.x * 128, n0 = blockIdx.y * 96;
    int tx = threadIdx.x;
    int warp = tx >> 5, lane = tx & 31;
    int wm = warp >> 1, wn = warp & 1;
    int gid = lane >> 2, tig = lane & 3;
    float acc[2][6][4] = {};
    for (int idx = tx; idx < 1536; idx += 256) {
        int r = idx / 12, c = idx - r * 12;
        *(uint4*)(smb + r * 104 + c * 8) = *(const uint4*)(A + (size_t)(m0 + r) * 96 + c * 8);
    }
    for (int idx = tx; idx < 1152; idx += 256) {
        int r = idx / 12, c = idx - r * 12;
        *(uint4*)(smb + (128 + r) * 104 + c * 8) = *(const uint4*)(Wt + (size_t)(n0 + r) * 96 + c * 8);
    }
    __syncthreads();
    __nv_bfloat16* w_s = smb + 128 * 104;
    unsigned a_u = (unsigned)__cvta_generic_to_shared(smb);
    #pragma unroll
    for (int ks = 0; ks < 6; ks++) {
        unsigned af[2][4];
        #pragma unroll
        for (int mt = 0; mt < 2; mt++)
            ldsm4(af[mt], a_u + 2u * ((wm * 32 + mt * 16 + (lane & 15)) * 104
                                      + ks * 16 + ((lane >> 4) << 3)));
        #pragma unroll
        for (int np = 0; np < 3; np++) {
            unsigned bf[4];
            ldsmB(bf, w_s + (wn * 48 + np * 16) * 104 + ks * 16, 104, lane);
            #pragma unroll
            for (int mt = 0; mt < 2; mt++) {
                mma16(acc[mt][np * 2], af[mt], bf);
                mma16(acc[mt][np * 2 + 1], af[mt], bf + 2);
            }
        }
    }
    #pragma unroll
    for (int mt = 0; mt < 2; mt++) {
        #pragma unroll
        for (int nt = 0; nt < 6; nt++) {
            int cc = n0 + wn * 48 + nt * 8 + tig * 2;
            float bb0 = bias[cc], bb1 = bias[cc + 1];
            #pragma unroll
            for (int half = 0; half < 2; half++) {
                int r = m0 + wm * 32 + mt * 16 + gid + half * 8;
                size_t idx = (size_t)r * Nn + cc;
                *(unsigned*)(Cout + idx) = pack2(acc[mt][nt][half * 2 + 0] + bb0,
                                                 acc[mt][nt][half * 2 + 1] + bb1);
            }
        }
    }
}

// ---------------- fused MLP: out = x1 + gelu(xn2@f1w+b1)@f2w + b2 ----------------
#define MLP_A  0
#define MLP_W  (64 * 104)
#define MLP_H  (MLP_W + 2 * 96 * 104)
#define MLP_SE (MLP_H + 4 * 64 * 104)
__global__ __launch_bounds__(256) void mlp_kernel(
    const __nv_bfloat16* __restrict__ xn2, const __nv_bfloat16* __restrict__ f1w,
    const float* __restrict__ fb1, const __nv_bfloat16* __restrict__ f2w,
    const float* __restrict__ fb2, const float* __restrict__ x1,
    float* __restrict__ out)
{
    extern __shared__ __nv_bfloat16 smb[];
    __nv_bfloat16* a_s = smb + MLP_A;
    __nv_bfloat16* h_s = smb + MLP_H;
    int m0 = blockIdx.x * 64;
    int tx = threadIdx.x;
    int warp = tx >> 5, lane = tx & 31;
    int wm = warp >> 1, wn = warp & 1;
    int gid = lane >> 2, tig = lane & 3;

    for (int idx = tx; idx < 768; idx += 256) {
        int r = idx / 12, c = idx - r * 12;
        *(uint4*)(a_s + r * 104 + c * 8) = *(const uint4*)(xn2 + (size_t)(m0 + r) * 96 + c * 8);
    }
    auto load_w = [&](int ph, int buf) {
        __nv_bfloat16* w_s = smb + MLP_W + buf * (96 * 104);
        const __nv_bfloat16* src = (ph < 4)
            ? f1w + (size_t)(ph * 96) * 96
            : f2w + (size_t)(ph - 4) * 96;
        size_t rstride = (ph < 4) ? 96 : 384;
        for (int idx = tx; idx < 1152; idx += 256) {
            int r = idx / 12, c = idx - r * 12;
            cpa16(w_s + r * 104 + c * 8, src + (size_t)r * rstride + c * 8, true);
        }
        cpa_commit();
    };
    load_w(0, 0);

    float acc[6][4] = {};
    unsigned a_u = (unsigned)__cvta_generic_to_shared(a_s);
    unsigned h_u = (unsigned)__cvta_generic_to_shared(h_s);

    for (int ph = 0; ph < 8; ph++) {
        cpa_wait<0>();
        __syncthreads();
        if (ph < 7) load_w(ph + 1, (ph + 1) & 1);
        __nv_bfloat16* w_s = smb + MLP_W + (ph & 1) * (96 * 104);
        if (ph < 4) {
            #pragma unroll
            for (int nt = 0; nt < 6; nt++)
                #pragma unroll
                for (int e = 0; e < 4; e++) acc[nt][e] = 0.f;
            #pragma unroll
            for (int ks = 0; ks < 6; ks++) {
                unsigned af[4];
                ldsm4(af, a_u + 2u * ((wm * 16 + (lane & 15)) * 104
                                      + ks * 16 + ((lane >> 4) << 3)));
                #pragma unroll
                for (int np = 0; np < 3; np++) {
                    unsigned bf[4];
                    ldsmB(bf, w_s + (wn * 48 + np * 16) * 104 + ks * 16, 104, lane);
                    mma16(acc[np * 2], af, bf);
                    mma16(acc[np * 2 + 1], af, bf + 2);
                }
            }
            __nv_bfloat16* hc = h_s + ph * (64 * 104);
            #pragma unroll
            for (int nt = 0; nt < 6; nt++) {
                int cc = wn * 48 + nt * 8 + tig * 2;
                float bb0 = fb1[ph * 96 + cc], bb1 = fb1[ph * 96 + cc + 1];
                #pragma unroll
                for (int half = 0; half < 2; half++) {
                    int rl = wm * 16 + gid + half * 8;
                    *(unsigned*)(hc + rl * 104 + cc) =
                        pack2(gelu_exact(acc[nt][half * 2 + 0] + bb0),
                              gelu_exact(acc[nt][half * 2 + 1] + bb1));
                }
            }
        } else {
            int kc = ph - 4;
            if (kc == 0) {
                #pragma unroll
                for (int nt = 0; nt < 6; nt++)
                    #pragma unroll
                    for (int e = 0; e < 4; e++) acc[nt][e] = 0.f;
            }
            unsigned hc_u = h_u + 2u * kc * (64 * 104);
            #pragma unroll
            for (int ks = 0; ks < 6; ks++) {
                unsigned af[4];
                ldsm4(af, hc_u + 2u * ((wm * 16 + (lane & 15)) * 104
                                       + ks * 16 + ((lane >> 4) << 3)));
                #pragma unroll
                for (int np = 0; np < 3; np++) {
                    unsigned bf[4];
                    ldsmB(bf, w_s + (wn * 48 + np * 16) * 104 + ks * 16, 104, lane);
                    mma16(acc[np * 2], af, bf);
                    mma16(acc[np * 2 + 1], af, bf + 2);
                }
            }
        }
    }
    #pragma unroll
    for (int nt = 0; nt < 6; nt++) {
        int cc = wn * 48 + nt * 8 + tig * 2;
        float bb0 = fb2[cc], bb1 = fb2[cc + 1];
        #pragma unroll
        for (int half = 0; half < 2; half++) {
            int r = m0 + wm * 16 + gid + half * 8;
            size_t idx = (size_t)r * 96 + cc;
            float2 r1 = *(const float2*)(x1 + idx);
            float2 o2;
            o2.x = r1.x + acc[nt][half * 2 + 0] + bb0;
            o2.y = r1.y + acc[nt][half * 2 + 1] + bb1;
            *(float2*)(out + idx) = o2;
        }
    }
}

// ---------------- proj GEMM + residual merge + fused LayerNorm2 ----------------
__global__ __launch_bounds__(256) void gemm_proj_ln(
    const __nv_bfloat16* __restrict__ A, const __nv_bfloat16* __restrict__ Wt,
    const float* __restrict__ bias,
    const float* __restrict__ res1, const __nv_bfloat16* __restrict__ res2,
    const float* __restrict__ att,
    const float* __restrict__ n2g, const float* __restrict__ n2b,
    float* __restrict__ x1, __nv_bfloat16* __restrict__ xn2)
{
    extern __shared__ __nv_bfloat16 smb[];
    __nv_bfloat16* a_s = smb;
    __nv_bfloat16* w_s = smb + 128 * 104;
    float* red_s = (float*)smb;
    float* red_q = red_s + 256;
    unsigned a_u = (unsigned)__cvta_generic_to_shared(a_s);
    int m0 = blockIdx.x * 128;
    int tx = threadIdx.x;
    int warp = tx >> 5, lane = tx & 31;
    int wm = warp >> 1, wn = warp & 1;
    int gid = lane >> 2, tig = lane & 3;
    float acc[2][6][4] = {};
    {
        for (int idx = tx; idx < 1536; idx += 256) {
            int r = idx / 12, c = idx - r * 12;
            *(uint4*)(a_s + r * 104 + c * 8) = *(const uint4*)(A + (size_t)(m0 + r) * 96 + c * 8);
        }
        for (int idx = tx; idx < 1152; idx += 256) {
            int r = idx / 12, c = idx - r * 12;
            *(uint4*)(w_s + r * 104 + c * 8) = *(const uint4*)(Wt + (size_t)r * 96 + c * 8);
        }
        __syncthreads();
        #pragma unroll
        for (int ks = 0; ks < 6; ks++) {
            unsigned af[2][4];
            #pragma unroll
            for (int mt = 0; mt < 2; mt++)
                ldsm4(af[mt], a_u + 2u * ((wm * 32 + mt * 16 + (lane & 15)) * 104
                                          + ks * 16 + ((lane >> 4) << 3)));
            #pragma unroll
            for (int np = 0; np < 3; np++) {
                unsigned bf[4];
                ldsmB(bf, w_s + (wn * 48 + np * 16) * 104 + ks * 16, 104, lane);
                #pragma unroll
                for (int mt = 0; mt < 2; mt++) {
                    mma16(acc[mt][np * 2], af[mt], bf);
                    mma16(acc[mt][np * 2 + 1], af[mt], bf + 2);
                }
            }
        }
    }
    __syncthreads();

    float rs[2][2] = {}, rq[2][2] = {};
    #pragma unroll
    for (int mt = 0; mt < 2; mt++) {
        #pragma unroll
        for (int nt = 0; nt < 6; nt++) {
            int cc = wn * 48 + nt * 8 + tig * 2;
            float bb0 = bias[cc], bb1 = bias[cc + 1];
            float a0 = att[cc] * 0.01f, a1 = att[cc + 1] * 0.01f;
            #pragma unroll
            for (int half = 0; half < 2; half++) {
                int r = m0 + wm * 32 + mt * 16 + gid + half * 8;
                size_t idx = (size_t)r * 96 + cc;
                float2 r1 = *(const float2*)(res1 + idx);
                float2 r2 = __bfloat1622float2(*(const __nv_bfloat162*)(res2 + idx));
                float v0 = r1.x + acc[mt][nt][half * 2 + 0] + bb0 + r2.x * a0;
                float v1 = r1.y + acc[mt][nt][half * 2 + 1] + bb1 + r2.y * a1;
                acc[mt][nt][half * 2 + 0] = v0;
                acc[mt][nt][half * 2 + 1] = v1;
                *(float2*)(x1 + idx) = make_float2(v0, v1);
                rs[mt][half] += v0 + v1;
                rq[mt][half] += v0 * v0 + v1 * v1;
            }
        }
    }
    #pragma unroll
    for (int mt = 0; mt < 2; mt++)
        #pragma unroll
        for (int half = 0; half < 2; half++) {
            float s = rs[mt][half], q = rq[mt][half];
            s += __shfl_xor_sync(0xffffffffu, s, 1);
            s += __shfl_xor_sync(0xffffffffu, s, 2);
            q += __shfl_xor_sync(0xffffffffu, q, 1);
            q += __shfl_xor_sync(0xffffffffu, q, 2);
            if (tig == 0) {
                int lr = wm * 32 + mt * 16 + half * 8 + gid;
                red_s[lr * 2 + wn] = s;
                red_q[lr * 2 + wn] = q;
            }
        }
    __syncthreads();
    #pragma unroll
    for (int mt = 0; mt < 2; mt++) {
        #pragma unroll
        for (int half = 0; half < 2; half++) {
            int lr = wm * 32 + mt * 16 + half * 8 + gid;
            float sum = red_s[lr * 2] + red_s[lr * 2 + 1];
            float sq  = red_q[lr * 2] + red_q[lr * 2 + 1];
            float mean = sum * (1.0f / 96.0f);
            float var = sq * (1.0f / 96.0f) - mean * mean;
            float inv = rsqrtf(var + 1e-5f);
            int r = m0 + lr;
            #pragma unroll
            for (int nt = 0; nt < 6; nt++) {
                int cc = wn * 48 + nt * 8 + tig * 2;
                float g0 = n2g[cc], g1 = n2g[cc + 1];
                float b0 = n2b[cc], b1 = n2b[cc + 1];
                float v0 = (acc[mt][nt][half * 2 + 0] - mean) * inv * g0 + b0;
                float v1 = (acc[mt][nt][half * 2 + 1] - mean) * inv * g1 + b1;
                *(unsigned*)(xn2 + (size_t)r * 96 + cc) = pack2(v0, v1);
            }
        }
    }
}

// ---------------- attention: block = (win, head, query-half); 4 chunks/block ----------------
#define OFF_Q  0
#define OFF_K  3072
#define OFF_V  27648
#define OFF_R1 44288
#define OFF_R2 45312
#define OFF_OR 46336
#define SMEM_ATTN 62720

__device__ __forceinline__ int wtok(int j, int base) {
    return ((j >> 6) << 12) + base + (((j >> 3) & 7) << 6) + (j & 7);
}

__global__ __launch_bounds__(512) void attn_kernel(
    const __nv_bfloat16* __restrict__ qkv, const __nv_bfloat16* __restrict__ biasb,
    __nv_bfloat16* __restrict__ o)
{
    extern __shared__ char smc[];
    __nv_bfloat16* q_s = (__nv_bfloat16*)(smc + OFF_Q);
    __nv_bfloat16* k_s = (__nv_bfloat16*)(smc + OFF_K);
    __nv_bfloat16* v_t = (__nv_bfloat16*)(smc + OFF_V);
    float* red1 = (float*)(smc + OFF_R1);
    float* red2 = (float*)(smc + OFF_R2);
    float* o_red = (float*)(smc + OFF_OR);
    unsigned q_u = (unsigned)__cvta_generic_to_shared(q_s);

    int blk = blockIdx.x;
    int qh = blk & 1;                  // query half: chunks 0-3 or 4-7
    int head = (blk >> 1) % 6;
    int win = blk / 12;
    int base = (win >> 3) * 512 + (win & 7) * 8;
    int tx = threadIdx.x;
    int warp = tx >> 5, lane = tx & 31;
    int gid = lane >> 2, tig = lane & 3;
    int wm = warp >> 2, wn = warp & 3;
    int r0 = wm * 16, j0 = wn * 128;

    // K/V loaded ONCE per block (shared across 4 query chunks)
    for (int idx = tx; idx < 1024; idx += 512) {
        int j = idx >> 1, half = idx & 1;
        int t = wtok(j, base);
        const __nv_bfloat16* p = qkv + (size_t)t * 288 + head * 16 + half * 8;
        *(uint4*)(k_s + j * 24 + half * 8) = *(const uint4*)(p + 96);
        uint4 v4 = *(const uint4*)(p + 192);
        const __nv_bfloat16* vp = (const __nv_bfloat16*)&v4;
        #pragma unroll
        for (int dd2 = 0; dd2 < 8; dd2++)
            v_t[(half * 8 + dd2) * 520 + j] = vp[dd2];
    }

    for (int qc = qh * 4; qc < qh * 4 + 4; qc++) {
        int m0 = qc * 64;
        if (tx < 128) {
            int i = tx >> 1, half = tx & 1;
            int t = wtok(m0 + i, base);
            uint4 raw = *(const uint4*)(qkv + (size_t)t * 288 + head * 16 + half * 8);
            const __nv_bfloat16* rp = (const __nv_bfloat16*)&raw;
            unsigned pk[4];
            #pragma unroll
            for (int e = 0; e < 4; e++)
                pk[e] = pack2(__bfloat162float(rp[e * 2]) * 0.25f,
                              __bfloat162float(rp[e * 2 + 1]) * 0.25f);
            *(uint4*)(q_s + i * 24 + half * 8) = *(uint4*)pk;
        }
        __syncthreads();

        float acc[16][4] = {};
        {
            unsigned aq[4];
            ldsm4(aq, q_u + 2u * ((r0 + (lane & 15)) * 24 + ((lane >> 4) << 3)));
            #pragma unroll
            for (int np = 0; np < 8; np++) {
                unsigned bf[4];
                ldsmB(bf, k_s + (j0 + np * 16) * 24, 24, lane);
                mma16(acc[np * 2], aq, bf);
                mma16(acc[np * 2 + 1], aq, bf + 2);
            }
            const __nv_bfloat16* bbA = biasb + ((size_t)head * 512 + (m0 + r0 + gid)) * 512 + j0 + tig * 2;
            const __nv_bfloat16* bbB = bbA + 8 * 512;
            #pragma unroll
            for (int nt = 0; nt < 16; nt++) {
                float2 fa = __bfloat1622float2(*(const __nv_bfloat162*)(bbA + nt * 8));
                float2 fb = __bfloat1622float2(*(const __nv_bfloat162*)(bbB + nt * 8));
                acc[nt][0] += fa.x; acc[nt][1] += fa.y;
                acc[nt][2] += fb.x; acc[nt][3] += fb.y;
            }
        }
        {
            float mA = -1e30f, mB = -1e30f;
            #pragma unroll
            for (int nt = 0; nt < 16; nt++) {
                mA = fmaxf(mA, fmaxf(acc[nt][0], acc[nt][1]));
                mB = fmaxf(mB, fmaxf(acc[nt][2], acc[nt][3]));
            }
            mA = fmaxf(mA, __shfl_xor_sync(0xffffffffu, mA, 1));
            mA = fmaxf(mA, __shfl_xor_sync(0xffffffffu, mA, 2));
            mB = fmaxf(mB, __shfl_xor_sync(0xffffffffu, mB, 1));
            mB = fmaxf(mB, __shfl_xor_sync(0xffffffffu, mB, 2));
            if (tig == 0) {
                red1[(r0 + gid) * 4 + wn] = mA;
                red1[(r0 + gid + 8) * 4 + wn] = mB;
            }
            __syncthreads();
            mA = fmaxf(fmaxf(red1[(r0 + gid) * 4 + 0], red1[(r0 + gid) * 4 + 1]),
                       fmaxf(red1[(r0 + gid) * 4 + 2], red1[(r0 + gid) * 4 + 3]));
            mB = fmaxf(fmaxf(red1[(r0 + gid + 8) * 4 + 0], red1[(r0 + gid + 8) * 4 + 1]),
                       fmaxf(red1[(r0 + gid + 8) * 4 + 2], red1[(r0 + gid + 8) * 4 + 3]));
            float sA = 0.f, sB = 0.f;
            #pragma unroll
            for (int nt = 0; nt < 16; nt++) {
                acc[nt][0] = __expf(acc[nt][0] - mA);
                acc[nt][1] = __expf(acc[nt][1] - mA);
                acc[nt][2] = __expf(acc[nt][2] - mB);
                acc[nt][3] = __expf(acc[nt][3] - mB);
                sA += acc[nt][0] + acc[nt][1];
                sB += acc[nt][2] + acc[nt][3];
            }
            sA += __shfl_xor_sync(0xffffffffu, sA, 1);
            sA += __shfl_xor_sync(0xffffffffu, sA, 2);
            sB += __shfl_xor_sync(0xffffffffu, sB, 1);
            sB += __shfl_xor_sync(0xffffffffu, sB, 2);
            if (tig == 0) {
                red2[(r0 + gid) * 4 + wn] = sA;
                red2[(r0 + gid + 8) * 4 + wn] = sB;
            }
            __syncthreads();
            sA = red2[(r0 + gid) * 4 + 0] + red2[(r0 + gid) * 4 + 1]
               + red2[(r0 + gid) * 4 + 2] + red2[(r0 + gid) * 4 + 3];
            sB = red2[(r0 + gid + 8) * 4 + 0] + red2[(r0 + gid + 8) * 4 + 1]
               + red2[(r0 + gid + 8) * 4 + 2] + red2[(r0 + gid + 8) * 4 + 3];
            float iA = 1.0f / sA, iB = 1.0f / sB;
            #pragma unroll
            for (int nt = 0; nt < 16; nt++) {
                acc[nt][0] *= iA; acc[nt][1] *= iA;
                acc[nt][2] *= iB; acc[nt][3] *= iB;
            }
        }

        float oa[2][4] = {};
        #pragma unroll
        for (int kk = 0; kk < 8; kk++) {
            unsigned af[4];
            af[0] = pack2(acc[2 * kk][0],     acc[2 * kk][1]);
            af[1] = pack2(acc[2 * kk][2],     acc[2 * kk][3]);
            af[2] = pack2(acc[2 * kk + 1][0], acc[2 * kk + 1][1]);
            af[3] = pack2(acc[2 * kk + 1][2], acc[2 * kk + 1][3]);
            unsigned bf[4];
            ldsmB(bf, v_t + j0 + kk * 16, 520, lane);
            mma16(oa[0], af, bf);
            mma16(oa[1], af, bf + 2);
        }
        {
            float* orp = o_red + (size_t)wn * 1024;
            #pragma unroll
            for (int dt = 0; dt < 2; dt++) {
                int dc = dt * 8 + tig * 2;
                *(float2*)(orp + (r0 + gid) * 16 + dc)     = make_float2(oa[dt][0], oa[dt][1]);
                *(float2*)(orp + (r0 + gid + 8) * 16 + dc) = make_float2(oa[dt][2], oa[dt][3]);
            }
        }
        __syncthreads();
        {
            int row = tx >> 3, d2 = tx & 7;
            int dim = d2 * 2;
            float v0 = 0.f, v1 = 0.f;
            #pragma unroll
            for (int p = 0; p < 4; p++) {
                v0 += o_red[p * 1024 + row * 16 + dim];
                v1 += o_red[p * 1024 + row * 16 + dim + 1];
            }
            int t = wtok(m0 + row, base);
            *(unsigned*)(o + (size_t)t * CCH + head * 16 + dim) = pack2(v0, v1);
        }
        __syncthreads();   // o_red reads done before next chunk's PV writes
    }
}

// ---------------- launch (round-13 champion schedule; attn grid 768) ----------------
extern "C" void kernel_launch(void* const* d_in, const int* in_sizes, int n_in,
                              void* d_out, int out_size)
{
    (void)in_sizes; (void)n_in; (void)out_size;
    const float* x       = (const float*)d_in[0];
    const float* n1g     = (const float*)d_in[1];
    const float* n1b     = (const float*)d_in[2];
    const float* qkv_w   = (const float*)d_in[3];
    const float* qkv_b   = (const float*)d_in[4];
    const float* rpbt    = (const float*)d_in[5];
    const float* proj_w  = (const float*)d_in[6];
    const float* proj_b  = (const float*)d_in[7];
    const float* conv1_w = (const float*)d_in[8];
    const float* conv1_b = (const float*)d_in[9];
    const float* conv2_w = (const float*)d_in[10];
    const float* conv2_b = (const float*)d_in[11];
    const float* ca1_w   = (const float*)d_in[12];
    const float* ca1_b   = (const float*)d_in[13];
    const float* ca2_w   = (const float*)d_in[14];
    const float* ca2_b   = (const float*)d_in[15];
    const float* n2g     = (const float*)d_in[16];
    const float* n2b     = (const float*)d_in[17];
    const float* fc1_w   = (const float*)d_in[18];
    const float* fc1_b   = (const float*)d_in[19];
    const float* fc2_w   = (const float*)d_in[20];
    const float* fc2_b   = (const float*)d_in[21];
    const int*   rpi     = (const int*)d_in[22];
    float* out = (float*)d_out;

    __nv_bfloat16 *xn, *y1, *y2, *qkvb, *biasb, *ob, *xn2, *w1r, *w2r, *qw, *pw, *f1w, *f2w;
    float *part, *att, *x1;
    cudaGetSymbolAddress((void**)&xn,    g_xn);
    cudaGetSymbolAddress((void**)&y1,    g_y1);
    cudaGetSymbolAddress((void**)&y2,    g_y2);
    cudaGetSymbolAddress((void**)&part,  g_part);
    cudaGetSymbolAddress((void**)&att,   g_att);
    cudaGetSymbolAddress((void**)&qkvb,  g_qkv);
    cudaGetSymbolAddress((void**)&biasb, g_bias);
    cudaGetSymbolAddress((void**)&ob,    g_o);
    cudaGetSymbolAddress((void**)&x1,    g_x1);
    cudaGetSymbolAddress((void**)&xn2,   g_xn2);
    cudaGetSymbolAddress((void**)&w1r,   g_w1r);
    cudaGetSymbolAddress((void**)&w2r,   g_w2r);
    cudaGetSymbolAddress((void**)&qw,    g_qw);
    cudaGetSymbolAddress((void**)&pw,    g_pw);
    cudaGetSymbolAddress((void**)&f1w,   g_f1w);
    cudaGetSymbolAddress((void**)&f2w,   g_f2w);

    const int SMEM_CONV1 = 2 * C1_SE * 2;
    const int SMEM_CONV2 = 2 * C2_SE * 2;
    const int SMEM_G128  = (128 + 96) * 104 * 2;
    const int SMEM_MLP   = MLP_SE * 2;

    static bool s_init = false;
    static cudaStream_t sW, sC;
    static cudaEvent_t eFork, eLn, eW, eConv;
    if (!s_init) {
        cudaStreamCreateWithFlags(&sW, cudaStreamNonBlocking);
        cudaStreamCreateWithFlags(&sC, cudaStreamNonBlocking);
        cudaEventCreateWithFlags(&eFork, cudaEventDisableTiming);
        cudaEventCreateWithFlags(&eLn,   cudaEventDisableTiming);
        cudaEventCreateWithFlags(&eW,    cudaEventDisableTiming);
        cudaEventCreateWithFlags(&eConv, cudaEventDisableTiming);
        cudaFuncSetAttribute(conv1_kernel, cudaFuncAttributeMaxDynamicSharedMemorySize, SMEM_CONV1);
        cudaFuncSetAttribute(conv2_kernel, cudaFuncAttributeMaxDynamicSharedMemorySize, SMEM_CONV2);
        cudaFuncSetAttribute(gemm_qkv, cudaFuncAttributeMaxDynamicSharedMemorySize, SMEM_G128);
        cudaFuncSetAttribute(gemm_proj_ln, cudaFuncAttributeMaxDynamicSharedMemorySize, SMEM_G128);
        cudaFuncSetAttribute(mlp_kernel, cudaFuncAttributeMaxDynamicSharedMemorySize, SMEM_MLP);
        cudaFuncSetAttribute(attn_kernel, cudaFuncAttributeMaxDynamicSharedMemorySize, SMEM_ATTN);
        s_init = true;
    }

    cudaEventRecord(eFork, 0);

    cudaStreamWaitEvent(sW, eFork, 0);
    setup_w_kernel<<<1080, 256, 0, sW>>>(qkv_w, proj_w, fc1_w, fc2_w, conv1_w, conv2_w,
                                         qw, pw, f1w, f2w, w1r, w2r);
    cudaEventRecord(eW, sW);

    ln_kernel<<<LTOK / 8, 256>>>(x, n1g, n1b, xn);
    cudaEventRecord(eLn, 0);

    cudaStreamWaitEvent(sC, eLn, 0);
    cudaStreamWaitEvent(sC, eW, 0);
    conv1_kernel<<<512, 256, SMEM_CONV1, sC>>>(xn, w1r, conv1_b, y1);
    conv2_kernel<<<512, 256, SMEM_CONV2, sC>>>(y1, w2r, conv2_b, y2, part);
    ca_kernel<<<1, CCH, 0, sC>>>(part, ca1_w, ca1_b, ca2_w, ca2_b, att);
    cudaEventRecord(eConv, sC);

    setup_bias_kernel<<<3072, 256>>>(rpi, rpbt, biasb);
    cudaStreamWaitEvent(0, eW, 0);
    gemm_qkv<<<dim3(LTOK / 128, 3), 256, SMEM_G128>>>(xn, qw, qkv_b, qkvb, 288);
    attn_kernel<<<NWIN * HEADS * 2, 512, SMEM_ATTN>>>(qkvb, biasb, ob);

    cudaStreamWaitEvent(0, eConv, 0);
    gemm_proj_ln<<<LTOK / 128, 256, SMEM_G128>>>(
        ob, pw, proj_b, x, y2, att, n2g, n2b, x1, xn2);
    mlp_kernel<<<LTOK / 64, 256, SMEM_MLP>>>(xn2, f1w, fc1_b, f2w, fc2_b, x1, out);
}